// round 3
// baseline (speedup 1.0000x reference)
#include <cuda_runtime.h>

#define NQ 300
#define CC 256
#define NH 8
#define HD 32
#define HW 1024
#define HID 512

typedef unsigned long long ull;

// ---------------- packed f32x2 helpers (sm_103a) ----------------
__device__ __forceinline__ ull pk2(float lo, float hi) {
    ull r; asm("mov.b64 %0,{%1,%2};" : "=l"(r) : "f"(lo), "f"(hi)); return r;
}
__device__ __forceinline__ void upk2(ull v, float& lo, float& hi) {
    asm("mov.b64 {%0,%1},%2;" : "=f"(lo), "=f"(hi) : "l"(v));
}
__device__ __forceinline__ ull add2(ull a, ull b) {
    ull r; asm("add.rn.f32x2 %0,%1,%2;" : "=l"(r) : "l"(a), "l"(b)); return r;
}
__device__ __forceinline__ ull mul2(ull a, ull b) {
    ull r; asm("mul.rn.f32x2 %0,%1,%2;" : "=l"(r) : "l"(a), "l"(b)); return r;
}
__device__ __forceinline__ void fma2(ull& d, ull a, ull b) {
    asm("fma.rn.f32x2 %0,%1,%2,%0;" : "+l"(d) : "l"(a), "l"(b));
}

// ---------------- scratch (device globals; no allocation) ----------------
__device__ float g_q[NQ * CC];
__device__ float g_k[HW * CC];
__device__ float g_v[HW * CC];
__device__ float g_s[HID * NQ];       // s[f][q] = W1[f]·ref[q] + b1[f]
__device__ float g_t[HID * HW];       // NEGATED: -(W1[f]·key_pos[k])
__device__ float g_w2p[HID * 16];     // W2 splatted pairs: [f][h] -> (w2,w2), natural h order
__device__ float g_wot[CC * CC];      // Wo transposed: [c][n]
__device__ float g_S[NQ * NH * HW];   // scores, layout [q][h][k]

// ---------------- prep: s/t tables, W2 splat, Wo transpose ----------------
__global__ void __launch_bounds__(128) prep_kernel(const float* __restrict__ ref,
                                                   const float* __restrict__ W1,
                                                   const float* __restrict__ b1,
                                                   const float* __restrict__ W2,
                                                   const float* __restrict__ Wo) {
    int f = blockIdx.x;
    int tid = threadIdx.x;
    float w1x = W1[2 * f], w1y = W1[2 * f + 1], bb = b1[f];
    for (int k = tid; k < HW; k += 128) {
        int kx = k & 31, ky = k >> 5;
        float px = (kx + 0.5f) * (1.0f / 32.0f);
        float py = (ky + 0.5f) * (1.0f / 32.0f);
        g_t[f * HW + k] = -(w1x * px + w1y * py);
    }
    for (int q = tid; q < NQ; q += 128) {
        g_s[f * NQ + q] = w1x * ref[2 * q] + w1y * ref[2 * q + 1] + bb;
    }
    if (tid < NH) {
        float w = W2[tid * HID + f];
        g_w2p[f * 16 + 2 * tid] = w;
        g_w2p[f * 16 + 2 * tid + 1] = w;
    }
    // Wo transpose: 512 blocks x 128 threads = 65536 = 256*256
    int idx = blockIdx.x * 128 + tid;
    int r = idx >> 8, c = idx & 255;
    g_wot[c * 256 + r] = Wo[idx];
}

// ---------------- fused QKV projections: out = (A1+A2) @ W^T + bias ----------------
// grid: (37 row-tiles [5 q | 16 k | 16 v], 4 col-tiles). 148 blocks = 1/SM.
__global__ void __launch_bounds__(256) qkv_gemm_kernel(const float* __restrict__ rq,
                                                       const float* __restrict__ qp,
                                                       const float* __restrict__ rs,
                                                       const float* __restrict__ sp,
                                                       const float* __restrict__ Wq,
                                                       const float* __restrict__ bq,
                                                       const float* __restrict__ Wk,
                                                       const float* __restrict__ bk,
                                                       const float* __restrict__ Wv,
                                                       const float* __restrict__ bv) {
    __shared__ float As[16][68];
    __shared__ float Bs[16][68];

    int mt = blockIdx.x;
    int n0 = blockIdx.y * 64;

    const float *A1, *A2, *W, *bias;
    float* out;
    int M, m0;
    if (mt < 5)       { A1 = rq; A2 = qp; W = Wq; bias = bq; out = g_q; M = NQ; m0 = mt * 64; }
    else if (mt < 21) { A1 = rs; A2 = sp; W = Wk; bias = bk; out = g_k; M = HW; m0 = (mt - 5) * 64; }
    else              { A1 = rs; A2 = sp; W = Wv; bias = bv; out = g_v; M = HW; m0 = (mt - 21) * 64; }

    int t = threadIdx.x;
    int tx = t & 15, ty = t >> 4;
    int r = t >> 2, c4 = t & 3;

    ull acc2[4][2];
#pragma unroll
    for (int i = 0; i < 4; ++i) { acc2[i][0] = 0ull; acc2[i][1] = 0ull; }

    for (int kc = 0; kc < 256; kc += 16) {
        int gm = m0 + r;
        if (gm >= M) gm = M - 1;
        float4 a = *(const float4*)&A1[gm * 256 + kc + c4 * 4];
        float4 a2 = *(const float4*)&A2[gm * 256 + kc + c4 * 4];
        a.x += a2.x; a.y += a2.y; a.z += a2.z; a.w += a2.w;
        As[c4 * 4 + 0][r] = a.x;
        As[c4 * 4 + 1][r] = a.y;
        As[c4 * 4 + 2][r] = a.z;
        As[c4 * 4 + 3][r] = a.w;

        float4 b = *(const float4*)&W[(n0 + r) * 256 + kc + c4 * 4];
        Bs[c4 * 4 + 0][r] = b.x;
        Bs[c4 * 4 + 1][r] = b.y;
        Bs[c4 * 4 + 2][r] = b.z;
        Bs[c4 * 4 + 3][r] = b.w;
        __syncthreads();

#pragma unroll
        for (int kk = 0; kk < 16; ++kk) {
            float4 av = *(const float4*)&As[kk][ty * 4];
            ulonglong2 bp = *(const ulonglong2*)&Bs[kk][tx * 4]; // row stride 272B: 16B-aligned
            ull a0 = pk2(av.x, av.x), a1 = pk2(av.y, av.y);
            ull a2p = pk2(av.z, av.z), a3 = pk2(av.w, av.w);
            fma2(acc2[0][0], a0, bp.x); fma2(acc2[0][1], a0, bp.y);
            fma2(acc2[1][0], a1, bp.x); fma2(acc2[1][1], a1, bp.y);
            fma2(acc2[2][0], a2p, bp.x); fma2(acc2[2][1], a2p, bp.y);
            fma2(acc2[3][0], a3, bp.x); fma2(acc2[3][1], a3, bp.y);
        }
        __syncthreads();
    }

    float4 b4 = *(const float4*)&bias[n0 + tx * 4];
#pragma unroll
    for (int i = 0; i < 4; ++i) {
        int gm = m0 + ty * 4 + i;
        if (gm < M) {
            float4 o;
            upk2(acc2[i][0], o.x, o.y);
            upk2(acc2[i][1], o.z, o.w);
            o.x += b4.x; o.y += b4.y; o.z += b4.z; o.w += b4.w;
            *(float4*)&out[gm * 256 + n0 + tx * 4] = o;
        }
    }
}

// ---------------- score kernel: S = scale*q.k + sum_f relu(s-t)*W2 ----------------
// tile = 8 queries x 64 keys; grid (16 ktiles, 38 qtiles) = 608 blocks.
// thread: q = t&7, kg = t>>3 (2 keys each, packed f32x2). Natural head order
// throughout: acc2[h] is head h in BOTH phases and at store.
__global__ void __launch_bounds__(256) score_kernel() {
    __shared__ float smem[512 + 4096 + 1024]; // 22528 B
    float* bufA = smem;          // phase1: [64d][8q]   phase2: [64f][8q]
    float* bufB = smem + 512;    // phase1: [64d][64k]  phase2: [64f][64k]
    float* bufC = smem + 4608;   // phase2: [64f][16] splatted W2 pairs (h0..h7)

    int k0 = blockIdx.x * 64;
    int q0 = blockIdx.y * 8;
    int t = threadIdx.x;
    int q = t & 7;
    int kg = t >> 3; // 0..31, keys k0+2*kg, +1

    ull acc2[8];
#pragma unroll
    for (int h = 0; h < 8; ++h) acc2[h] = 0ull;

    // ----- phase 1: logits -----
#pragma unroll
    for (int c = 0; c < 4; ++c) {
        if (t < 128) {
            int qr = t >> 4, d4 = t & 15;
            int gq = q0 + qr;
            if (gq > NQ - 1) gq = NQ - 1;
            float4 a = *(const float4*)&g_q[gq * 256 + c * 64 + d4 * 4];
            bufA[(d4 * 4 + 0) * 8 + qr] = a.x;
            bufA[(d4 * 4 + 1) * 8 + qr] = a.y;
            bufA[(d4 * 4 + 2) * 8 + qr] = a.z;
            bufA[(d4 * 4 + 3) * 8 + qr] = a.w;
        }
#pragma unroll
        for (int j = 0; j < 4; ++j) {
            int idx = t + j * 256;
            int kr = idx >> 4, d4 = idx & 15;
            float4 b = *(const float4*)&g_k[(k0 + kr) * 256 + c * 64 + d4 * 4];
            bufB[(d4 * 4 + 0) * 64 + kr] = b.x;
            bufB[(d4 * 4 + 1) * 64 + kr] = b.y;
            bufB[(d4 * 4 + 2) * 64 + kr] = b.z;
            bufB[(d4 * 4 + 3) * 64 + kr] = b.w;
        }
        __syncthreads();
#pragma unroll
        for (int h2 = 0; h2 < 2; ++h2) {
#pragma unroll 8
            for (int dl = 0; dl < 32; ++dl) {
                int d = h2 * 32 + dl;
                float qv = bufA[d * 8 + q];
                ull kp = *(const ull*)&bufB[d * 64 + kg * 2];
                fma2(acc2[c * 2 + h2], pk2(qv, qv), kp);
            }
        }
        __syncthreads();
    }

    {
        const float scale = 0.17677669529663688f; // 32^-0.5
        ull sc = pk2(scale, scale);
#pragma unroll
        for (int h = 0; h < 8; ++h) acc2[h] = mul2(acc2[h], sc);
    }

    // ----- phase 2: CPB bias -----
    for (int fc = 0; fc < 8; ++fc) {
        int f0 = fc * 64;
#pragma unroll
        for (int j = 0; j < 2; ++j) {
            int idx = t + j * 256;
            int fr = idx >> 3, qi = idx & 7;
            int gq = q0 + qi;
            if (gq > NQ - 1) gq = NQ - 1;
            bufA[fr * 8 + qi] = g_s[(f0 + fr) * NQ + gq];
        }
#pragma unroll
        for (int j = 0; j < 4; ++j) {
            int idx = t + j * 256;
            int fr = idx >> 4, k4 = idx & 15;
            *(float4*)&bufB[fr * 64 + k4 * 4] =
                *(const float4*)&g_t[(f0 + fr) * HW + k0 + k4 * 4];
        }
        {
            int fr = t >> 2, part = t & 3;
            *(float4*)&bufC[fr * 16 + part * 4] =
                *(const float4*)&g_w2p[(f0 + fr) * 16 + part * 4];
        }
        __syncthreads();

#pragma unroll 4
        for (int fl = 0; fl < 64; ++fl) {
            float sv = bufA[fl * 8 + q];
            ull tp = *(const ull*)&bufB[fl * 64 + kg * 2]; // negated t
            ull x2 = add2(pk2(sv, sv), tp);                // s - t (packed over 2 keys)
            float x0, x1;
            upk2(x2, x0, x1);
            x0 = fmaxf(x0, 0.0f);
            x1 = fmaxf(x1, 0.0f);
            ull xx = pk2(x0, x1);
            // natural head order: pair for head h at bufC[fl*16 + 2h] (8B aligned)
#pragma unroll
            for (int h = 0; h < 8; ++h) {
                ull wp = *(const ull*)&bufC[fl * 16 + 2 * h];
                fma2(acc2[h], xx, wp);
            }
        }
        __syncthreads();
    }

    // ----- store (natural order) -----
    int gq = q0 + q;
    if (gq < NQ) {
#pragma unroll
        for (int h = 0; h < 8; ++h) {
            float lo, hi;
            upk2(acc2[h], lo, hi);
            float2 o = {lo, hi};
            *(float2*)&g_S[(gq * 8 + h) * HW + k0 + kg * 2] = o;
        }
    }
}

// ---------------- softmax + PV + output projection: 4 queries per block ----------------
__global__ void __launch_bounds__(256) softmax_pv_out_kernel(const float* __restrict__ bo,
                                                             float* __restrict__ out) {
    extern __shared__ float p_sm[]; // 4*8*1024 floats = 128 KB
    __shared__ float ctx[4][CC];
    __shared__ float rden[32];

    int tid = threadIdx.x;
    int q0 = blockIdx.x * 4;

    // stage S for 4 queries
    {
        const float4* src = (const float4*)&g_S[q0 * 8192];
        float4* dst = (float4*)p_sm;
        for (int i = tid; i < 8192; i += 256) dst[i] = src[i];
    }
    __syncthreads();

    int warp = tid >> 5, lane = tid & 31;
#pragma unroll
    for (int rr = 0; rr < 4; ++rr) {
        int row = rr * 8 + warp; // row = qi*8 + h
        float* p = p_sm + row * 1024;
        float m = -1e30f;
        for (int i = lane; i < 1024; i += 32) m = fmaxf(m, p[i]);
#pragma unroll
        for (int o = 16; o; o >>= 1) m = fmaxf(m, __shfl_xor_sync(0xffffffffu, m, o));
        float s = 0.0f;
        for (int i = lane; i < 1024; i += 32) {
            float e = __expf(p[i] - m);
            p[i] = e;
            s += e;
        }
#pragma unroll
        for (int o = 16; o; o >>= 1) s += __shfl_xor_sync(0xffffffffu, s, o);
        if (lane == 0) rden[row] = 1.0f / s;
    }
    __syncthreads();

    // PV: thread = (h=warp, d=lane)
    {
        int h = warp, d = lane;
        float a0 = 0.f, a1 = 0.f, a2 = 0.f, a3 = 0.f;
        const float* vp = g_v + h * 32 + d;
        const float* p0 = p_sm + (0 * 8 + h) * 1024;
        const float* p1 = p_sm + (1 * 8 + h) * 1024;
        const float* p2 = p_sm + (2 * 8 + h) * 1024;
        const float* p3 = p_sm + (3 * 8 + h) * 1024;
#pragma unroll 2
        for (int k = 0; k < 1024; k += 4) {
            float4 q0v = *(const float4*)&p0[k];
            float4 q1v = *(const float4*)&p1[k];
            float4 q2v = *(const float4*)&p2[k];
            float4 q3v = *(const float4*)&p3[k];
            float v0 = vp[(k + 0) * 256];
            float v1 = vp[(k + 1) * 256];
            float v2 = vp[(k + 2) * 256];
            float v3 = vp[(k + 3) * 256];
            a0 = fmaf(q0v.x, v0, a0); a0 = fmaf(q0v.y, v1, a0);
            a0 = fmaf(q0v.z, v2, a0); a0 = fmaf(q0v.w, v3, a0);
            a1 = fmaf(q1v.x, v0, a1); a1 = fmaf(q1v.y, v1, a1);
            a1 = fmaf(q1v.z, v2, a1); a1 = fmaf(q1v.w, v3, a1);
            a2 = fmaf(q2v.x, v0, a2); a2 = fmaf(q2v.y, v1, a2);
            a2 = fmaf(q2v.z, v2, a2); a2 = fmaf(q2v.w, v3, a2);
            a3 = fmaf(q3v.x, v0, a3); a3 = fmaf(q3v.y, v1, a3);
            a3 = fmaf(q3v.z, v2, a3); a3 = fmaf(q3v.w, v3, a3);
        }
        ctx[0][h * 32 + d] = a0 * rden[0 * 8 + h];
        ctx[1][h * 32 + d] = a1 * rden[1 * 8 + h];
        ctx[2][h * 32 + d] = a2 * rden[2 * 8 + h];
        ctx[3][h * 32 + d] = a3 * rden[3 * 8 + h];
    }
    __syncthreads();

    // output projection: out[q][n] = sum_c ctx[q][c] * WoT[c][n] + bo[n], n = tid
    {
        float acc0 = 0.f, acc1 = 0.f, acc2a = 0.f, acc3 = 0.f;
        const float* wt = g_wot + tid;
#pragma unroll 4
        for (int c = 0; c < 256; ++c) {
            float w = wt[c * 256];
            acc0 = fmaf(ctx[0][c], w, acc0);
            acc1 = fmaf(ctx[1][c], w, acc1);
            acc2a = fmaf(ctx[2][c], w, acc2a);
            acc3 = fmaf(ctx[3][c], w, acc3);
        }
        float bb = bo[tid];
        out[(q0 + 0) * 256 + tid] = acc0 + bb;
        out[(q0 + 1) * 256 + tid] = acc1 + bb;
        out[(q0 + 2) * 256 + tid] = acc2a + bb;
        out[(q0 + 3) * 256 + tid] = acc3 + bb;
    }
}

// ---------------- launch ----------------
extern "C" void kernel_launch(void* const* d_in, const int* in_sizes, int n_in,
                              void* d_out, int out_size) {
    const float* raw_query = (const float*)d_in[0];
    const float* query_pos = (const float*)d_in[1];
    const float* ref_pts   = (const float*)d_in[2];
    const float* raw_src   = (const float*)d_in[3];
    const float* src_pos   = (const float*)d_in[4];
    const float* Wq = (const float*)d_in[5];
    const float* bq = (const float*)d_in[6];
    const float* Wk = (const float*)d_in[7];
    const float* bk = (const float*)d_in[8];
    const float* Wv = (const float*)d_in[9];
    const float* bv = (const float*)d_in[10];
    const float* Wo = (const float*)d_in[11];
    const float* bo = (const float*)d_in[12];
    const float* W1 = (const float*)d_in[13];
    const float* b1 = (const float*)d_in[14];
    const float* W2 = (const float*)d_in[15];
    float* out = (float*)d_out;

    prep_kernel<<<512, 128>>>(ref_pts, W1, b1, W2, Wo);

    qkv_gemm_kernel<<<dim3(37, 4), 256>>>(raw_query, query_pos, raw_src, src_pos,
                                          Wq, bq, Wk, bk, Wv, bv);

    score_kernel<<<dim3(16, 38), 256>>>();

    cudaFuncSetAttribute(softmax_pv_out_kernel,
                         cudaFuncAttributeMaxDynamicSharedMemorySize,
                         4 * 8 * 1024 * (int)sizeof(float));
    softmax_pv_out_kernel<<<75, 256, 4 * 8 * 1024 * sizeof(float)>>>(bo, out);
}

// round 4
// speedup vs baseline: 1.3568x; 1.3568x over previous
#include <cuda_runtime.h>

#define NQ 300
#define CC 256
#define NH 8
#define HD 32
#define HW 1024
#define HID 512

typedef unsigned long long ull;

// ---------------- packed f32x2 helpers (sm_103a) ----------------
__device__ __forceinline__ ull pk2(float lo, float hi) {
    ull r; asm("mov.b64 %0,{%1,%2};" : "=l"(r) : "f"(lo), "f"(hi)); return r;
}
__device__ __forceinline__ void upk2(ull v, float& lo, float& hi) {
    asm("mov.b64 {%0,%1},%2;" : "=f"(lo), "=f"(hi) : "l"(v));
}
__device__ __forceinline__ ull add2(ull a, ull b) {
    ull r; asm("add.rn.f32x2 %0,%1,%2;" : "=l"(r) : "l"(a), "l"(b)); return r;
}
__device__ __forceinline__ ull mul2(ull a, ull b) {
    ull r; asm("mul.rn.f32x2 %0,%1,%2;" : "=l"(r) : "l"(a), "l"(b)); return r;
}
__device__ __forceinline__ void fma2(ull& d, ull a, ull b) {
    asm("fma.rn.f32x2 %0,%1,%2,%0;" : "+l"(d) : "l"(a), "l"(b));
}

// ---------------- scratch (device globals; no allocation) ----------------
__device__ float g_q[NQ * CC];
__device__ float g_k[HW * CC];
__device__ float g_v[HW * CC];
__device__ float g_s[HID * NQ];       // s[f][q] = W1[f]·ref[q] + b1[f]
__device__ float g_t[HID * HW];       // NEGATED: -(W1[f]·key_pos[k])
__device__ float g_w2p[HID * 16];     // W2 splatted pairs: [f][h] -> (w2,w2), natural h order
__device__ float g_wot[CC * CC];      // Wo transposed: [c][n]
__device__ float g_S[NQ * NH * HW];   // scores -> (in-place) softmax probs, layout [q][h][k]
__device__ float g_ctx[NQ * CC];      // attention context

// ---------------- prep: s/t tables, W2 splat, Wo transpose ----------------
__global__ void __launch_bounds__(128) prep_kernel(const float* __restrict__ ref,
                                                   const float* __restrict__ W1,
                                                   const float* __restrict__ b1,
                                                   const float* __restrict__ W2,
                                                   const float* __restrict__ Wo) {
    int f = blockIdx.x;
    int tid = threadIdx.x;
    float w1x = W1[2 * f], w1y = W1[2 * f + 1], bb = b1[f];
    for (int k = tid; k < HW; k += 128) {
        int kx = k & 31, ky = k >> 5;
        float px = (kx + 0.5f) * (1.0f / 32.0f);
        float py = (ky + 0.5f) * (1.0f / 32.0f);
        g_t[f * HW + k] = -(w1x * px + w1y * py);
    }
    for (int q = tid; q < NQ; q += 128) {
        g_s[f * NQ + q] = w1x * ref[2 * q] + w1y * ref[2 * q + 1] + bb;
    }
    if (tid < NH) {
        float w = W2[tid * HID + f];
        g_w2p[f * 16 + 2 * tid] = w;
        g_w2p[f * 16 + 2 * tid + 1] = w;
    }
    int idx = blockIdx.x * 128 + tid;
    int r = idx >> 8, c = idx & 255;
    g_wot[c * 256 + r] = Wo[idx];
}

// ---------------- fused QKV projections (unchanged from R3, passing) ----------------
__global__ void __launch_bounds__(256) qkv_gemm_kernel(const float* __restrict__ rq,
                                                       const float* __restrict__ qp,
                                                       const float* __restrict__ rs,
                                                       const float* __restrict__ sp,
                                                       const float* __restrict__ Wq,
                                                       const float* __restrict__ bq,
                                                       const float* __restrict__ Wk,
                                                       const float* __restrict__ bk,
                                                       const float* __restrict__ Wv,
                                                       const float* __restrict__ bv) {
    __shared__ float As[16][68];
    __shared__ float Bs[16][68];

    int mt = blockIdx.x;
    int n0 = blockIdx.y * 64;

    const float *A1, *A2, *W, *bias;
    float* out;
    int M, m0;
    if (mt < 5)       { A1 = rq; A2 = qp; W = Wq; bias = bq; out = g_q; M = NQ; m0 = mt * 64; }
    else if (mt < 21) { A1 = rs; A2 = sp; W = Wk; bias = bk; out = g_k; M = HW; m0 = (mt - 5) * 64; }
    else              { A1 = rs; A2 = sp; W = Wv; bias = bv; out = g_v; M = HW; m0 = (mt - 21) * 64; }

    int t = threadIdx.x;
    int tx = t & 15, ty = t >> 4;
    int r = t >> 2, c4 = t & 3;

    ull acc2[4][2];
#pragma unroll
    for (int i = 0; i < 4; ++i) { acc2[i][0] = 0ull; acc2[i][1] = 0ull; }

    for (int kc = 0; kc < 256; kc += 16) {
        int gm = m0 + r;
        if (gm >= M) gm = M - 1;
        float4 a = *(const float4*)&A1[gm * 256 + kc + c4 * 4];
        float4 a2 = *(const float4*)&A2[gm * 256 + kc + c4 * 4];
        a.x += a2.x; a.y += a2.y; a.z += a2.z; a.w += a2.w;
        As[c4 * 4 + 0][r] = a.x;
        As[c4 * 4 + 1][r] = a.y;
        As[c4 * 4 + 2][r] = a.z;
        As[c4 * 4 + 3][r] = a.w;

        float4 b = *(const float4*)&W[(n0 + r) * 256 + kc + c4 * 4];
        Bs[c4 * 4 + 0][r] = b.x;
        Bs[c4 * 4 + 1][r] = b.y;
        Bs[c4 * 4 + 2][r] = b.z;
        Bs[c4 * 4 + 3][r] = b.w;
        __syncthreads();

#pragma unroll
        for (int kk = 0; kk < 16; ++kk) {
            float4 av = *(const float4*)&As[kk][ty * 4];
            ulonglong2 bp = *(const ulonglong2*)&Bs[kk][tx * 4];
            ull a0 = pk2(av.x, av.x), a1 = pk2(av.y, av.y);
            ull a2p = pk2(av.z, av.z), a3 = pk2(av.w, av.w);
            fma2(acc2[0][0], a0, bp.x); fma2(acc2[0][1], a0, bp.y);
            fma2(acc2[1][0], a1, bp.x); fma2(acc2[1][1], a1, bp.y);
            fma2(acc2[2][0], a2p, bp.x); fma2(acc2[2][1], a2p, bp.y);
            fma2(acc2[3][0], a3, bp.x); fma2(acc2[3][1], a3, bp.y);
        }
        __syncthreads();
    }

    float4 b4 = *(const float4*)&bias[n0 + tx * 4];
#pragma unroll
    for (int i = 0; i < 4; ++i) {
        int gm = m0 + ty * 4 + i;
        if (gm < M) {
            float4 o;
            upk2(acc2[i][0], o.x, o.y);
            upk2(acc2[i][1], o.z, o.w);
            o.x += b4.x; o.y += b4.y; o.z += b4.z; o.w += b4.w;
            *(float4*)&out[gm * 256 + n0 + tx * 4] = o;
        }
    }
}

// ---------------- score kernel (unchanged from R3, passing) ----------------
__global__ void __launch_bounds__(256) score_kernel() {
    __shared__ float smem[512 + 4096 + 1024];
    float* bufA = smem;
    float* bufB = smem + 512;
    float* bufC = smem + 4608;

    int k0 = blockIdx.x * 64;
    int q0 = blockIdx.y * 8;
    int t = threadIdx.x;
    int q = t & 7;
    int kg = t >> 3;

    ull acc2[8];
#pragma unroll
    for (int h = 0; h < 8; ++h) acc2[h] = 0ull;

#pragma unroll
    for (int c = 0; c < 4; ++c) {
        if (t < 128) {
            int qr = t >> 4, d4 = t & 15;
            int gq = q0 + qr;
            if (gq > NQ - 1) gq = NQ - 1;
            float4 a = *(const float4*)&g_q[gq * 256 + c * 64 + d4 * 4];
            bufA[(d4 * 4 + 0) * 8 + qr] = a.x;
            bufA[(d4 * 4 + 1) * 8 + qr] = a.y;
            bufA[(d4 * 4 + 2) * 8 + qr] = a.z;
            bufA[(d4 * 4 + 3) * 8 + qr] = a.w;
        }
#pragma unroll
        for (int j = 0; j < 4; ++j) {
            int idx = t + j * 256;
            int kr = idx >> 4, d4 = idx & 15;
            float4 b = *(const float4*)&g_k[(k0 + kr) * 256 + c * 64 + d4 * 4];
            bufB[(d4 * 4 + 0) * 64 + kr] = b.x;
            bufB[(d4 * 4 + 1) * 64 + kr] = b.y;
            bufB[(d4 * 4 + 2) * 64 + kr] = b.z;
            bufB[(d4 * 4 + 3) * 64 + kr] = b.w;
        }
        __syncthreads();
#pragma unroll
        for (int h2 = 0; h2 < 2; ++h2) {
#pragma unroll 8
            for (int dl = 0; dl < 32; ++dl) {
                int d = h2 * 32 + dl;
                float qv = bufA[d * 8 + q];
                ull kp = *(const ull*)&bufB[d * 64 + kg * 2];
                fma2(acc2[c * 2 + h2], pk2(qv, qv), kp);
            }
        }
        __syncthreads();
    }

    {
        const float scale = 0.17677669529663688f;
        ull sc = pk2(scale, scale);
#pragma unroll
        for (int h = 0; h < 8; ++h) acc2[h] = mul2(acc2[h], sc);
    }

    for (int fc = 0; fc < 8; ++fc) {
        int f0 = fc * 64;
#pragma unroll
        for (int j = 0; j < 2; ++j) {
            int idx = t + j * 256;
            int fr = idx >> 3, qi = idx & 7;
            int gq = q0 + qi;
            if (gq > NQ - 1) gq = NQ - 1;
            bufA[fr * 8 + qi] = g_s[(f0 + fr) * NQ + gq];
        }
#pragma unroll
        for (int j = 0; j < 4; ++j) {
            int idx = t + j * 256;
            int fr = idx >> 4, k4 = idx & 15;
            *(float4*)&bufB[fr * 64 + k4 * 4] =
                *(const float4*)&g_t[(f0 + fr) * HW + k0 + k4 * 4];
        }
        {
            int fr = t >> 2, part = t & 3;
            *(float4*)&bufC[fr * 16 + part * 4] =
                *(const float4*)&g_w2p[(f0 + fr) * 16 + part * 4];
        }
        __syncthreads();

#pragma unroll 4
        for (int fl = 0; fl < 64; ++fl) {
            float sv = bufA[fl * 8 + q];
            ull tp = *(const ull*)&bufB[fl * 64 + kg * 2];
            ull x2 = add2(pk2(sv, sv), tp);
            float x0, x1;
            upk2(x2, x0, x1);
            x0 = fmaxf(x0, 0.0f);
            x1 = fmaxf(x1, 0.0f);
            ull xx = pk2(x0, x1);
#pragma unroll
            for (int h = 0; h < 8; ++h) {
                ull wp = *(const ull*)&bufC[fl * 16 + 2 * h];
                fma2(acc2[h], xx, wp);
            }
        }
        __syncthreads();
    }

    int gq = q0 + q;
    if (gq < NQ) {
#pragma unroll
        for (int h = 0; h < 8; ++h) {
            float lo, hi;
            upk2(acc2[h], lo, hi);
            float2 o = {lo, hi};
            *(float2*)&g_S[(gq * 8 + h) * HW + k0 + kg * 2] = o;
        }
    }
}

// ---------------- softmax: in-place on g_S. grid=300 (one query), warp=head ----------------
__global__ void __launch_bounds__(256) softmax_kernel() {
    int q = blockIdx.x;
    int warp = threadIdx.x >> 5, lane = threadIdx.x & 31;
    float4* rp = (float4*)&g_S[(q * 8 + warp) * 1024];

    float4 r[8];
#pragma unroll
    for (int j = 0; j < 8; ++j) r[j] = rp[lane + 32 * j];

    float m = -1e30f;
#pragma unroll
    for (int j = 0; j < 8; ++j) {
        m = fmaxf(m, fmaxf(fmaxf(r[j].x, r[j].y), fmaxf(r[j].z, r[j].w)));
    }
#pragma unroll
    for (int o = 16; o; o >>= 1) m = fmaxf(m, __shfl_xor_sync(0xffffffffu, m, o));

    float s = 0.0f;
#pragma unroll
    for (int j = 0; j < 8; ++j) {
        r[j].x = __expf(r[j].x - m); s += r[j].x;
        r[j].y = __expf(r[j].y - m); s += r[j].y;
        r[j].z = __expf(r[j].z - m); s += r[j].z;
        r[j].w = __expf(r[j].w - m); s += r[j].w;
    }
#pragma unroll
    for (int o = 16; o; o >>= 1) s += __shfl_xor_sync(0xffffffffu, s, o);
    float inv = 1.0f / s;

#pragma unroll
    for (int j = 0; j < 8; ++j) {
        r[j].x *= inv; r[j].y *= inv; r[j].z *= inv; r[j].w *= inv;
        rp[lane + 32 * j] = r[j];
    }
}

// ---------------- PV GEMM: ctx[q, col] = sum_k P[q,h(col),k] * v[k,col] ----------------
// grid (4 coltiles, 38 qtiles) = 152 blocks; 128 threads; tile 8q x 64cols.
__global__ void __launch_bounds__(128) pv_kernel() {
    __shared__ float Psm[16 * 64];  // [h2*8q][64k]
    __shared__ float vsm[64 * 64];  // [64k][64c]

    int by = blockIdx.x;           // coltile (heads 2by, 2by+1)
    int q0 = blockIdx.y * 8;
    int t = threadIdx.x;
    int qg = t >> 5;               // 0..3, covers q qg*2, qg*2+1
    int cp = t & 31;
    int h = cp >> 4;               // 0/1 local head
    int cpl = cp & 15;             // colpair within head

    ull acc2[2] = {0ull, 0ull};

    for (int kc = 0; kc < 1024; kc += 64) {
        // stage P chunk: 16 rows (h*8+q) x 64 k
#pragma unroll
        for (int it = 0; it < 2; ++it) {
            int idx = t + it * 128;
            int row = idx >> 4, kk4 = idx & 15;
            int q_l = row & 7, hh = row >> 3;
            int gq = q0 + q_l; if (gq > NQ - 1) gq = NQ - 1;
            *(float4*)&Psm[(hh * 8 + q_l) * 64 + kk4 * 4] =
                *(const float4*)&g_S[(gq * 8 + 2 * by + hh) * 1024 + kc + kk4 * 4];
        }
        // stage v chunk: 64 k x 64 c
#pragma unroll
        for (int it = 0; it < 8; ++it) {
            int idx = t + it * 128;
            int row = idx >> 4, c4 = idx & 15;
            *(float4*)&vsm[row * 64 + c4 * 4] =
                *(const float4*)&g_v[(kc + row) * 256 + by * 64 + c4 * 4];
        }
        __syncthreads();

#pragma unroll 4
        for (int kk = 0; kk < 64; kk += 4) {
            float4 p0 = *(const float4*)&Psm[(h * 8 + qg * 2 + 0) * 64 + kk];
            float4 p1 = *(const float4*)&Psm[(h * 8 + qg * 2 + 1) * 64 + kk];
            float p0a[4] = {p0.x, p0.y, p0.z, p0.w};
            float p1a[4] = {p1.x, p1.y, p1.z, p1.w};
#pragma unroll
            for (int j = 0; j < 4; ++j) {
                ull vv = *(const ull*)&vsm[(kk + j) * 64 + h * 32 + cpl * 2];
                fma2(acc2[0], pk2(p0a[j], p0a[j]), vv);
                fma2(acc2[1], pk2(p1a[j], p1a[j]), vv);
            }
        }
        __syncthreads();
    }

#pragma unroll
    for (int i = 0; i < 2; ++i) {
        int gq = q0 + qg * 2 + i;
        if (gq < NQ) {
            float lo, hi;
            upk2(acc2[i], lo, hi);
            float2 o = {lo, hi};
            *(float2*)&g_ctx[gq * 256 + by * 64 + h * 32 + cpl * 2] = o;
        }
    }
}

// ---------------- out-proj GEMM: out = ctx @ WoT + bo ----------------
// grid (4 coltiles, 38 qtiles); 128 threads; tile 8q x 64n over k=256.
__global__ void __launch_bounds__(128) outproj_kernel(const float* __restrict__ bo,
                                                      float* __restrict__ out) {
    __shared__ float Csm[8 * 64];   // [8q][64k]
    __shared__ float wsm[64 * 64];  // [64k][64n]

    int by = blockIdx.x;
    int q0 = blockIdx.y * 8;
    int t = threadIdx.x;
    int qg = t >> 5;
    int cp = t & 31;

    ull acc2[2] = {0ull, 0ull};

    for (int kc = 0; kc < 256; kc += 64) {
        {
            int row = t >> 4, kk4 = t & 15;  // 128 threads = 8 rows x 16 quads
            int gq = q0 + row; if (gq > NQ - 1) gq = NQ - 1;
            *(float4*)&Csm[row * 64 + kk4 * 4] =
                *(const float4*)&g_ctx[gq * 256 + kc + kk4 * 4];
        }
#pragma unroll
        for (int it = 0; it < 8; ++it) {
            int idx = t + it * 128;
            int row = idx >> 4, c4 = idx & 15;
            *(float4*)&wsm[row * 64 + c4 * 4] =
                *(const float4*)&g_wot[(kc + row) * 256 + by * 64 + c4 * 4];
        }
        __syncthreads();

#pragma unroll 4
        for (int kk = 0; kk < 64; kk += 4) {
            float4 c0 = *(const float4*)&Csm[(qg * 2 + 0) * 64 + kk];
            float4 c1 = *(const float4*)&Csm[(qg * 2 + 1) * 64 + kk];
            float c0a[4] = {c0.x, c0.y, c0.z, c0.w};
            float c1a[4] = {c1.x, c1.y, c1.z, c1.w};
#pragma unroll
            for (int j = 0; j < 4; ++j) {
                ull ww = *(const ull*)&wsm[(kk + j) * 64 + cp * 2];
                fma2(acc2[0], pk2(c0a[j], c0a[j]), ww);
                fma2(acc2[1], pk2(c1a[j], c1a[j]), ww);
            }
        }
        __syncthreads();
    }

    float b0 = bo[by * 64 + cp * 2], b1 = bo[by * 64 + cp * 2 + 1];
#pragma unroll
    for (int i = 0; i < 2; ++i) {
        int gq = q0 + qg * 2 + i;
        if (gq < NQ) {
            float lo, hi;
            upk2(acc2[i], lo, hi);
            float2 o = {lo + b0, hi + b1};
            *(float2*)&out[gq * 256 + by * 64 + cp * 2] = o;
        }
    }
}

// ---------------- launch ----------------
extern "C" void kernel_launch(void* const* d_in, const int* in_sizes, int n_in,
                              void* d_out, int out_size) {
    const float* raw_query = (const float*)d_in[0];
    const float* query_pos = (const float*)d_in[1];
    const float* ref_pts   = (const float*)d_in[2];
    const float* raw_src   = (const float*)d_in[3];
    const float* src_pos   = (const float*)d_in[4];
    const float* Wq = (const float*)d_in[5];
    const float* bq = (const float*)d_in[6];
    const float* Wk = (const float*)d_in[7];
    const float* bk = (const float*)d_in[8];
    const float* Wv = (const float*)d_in[9];
    const float* bv = (const float*)d_in[10];
    const float* Wo = (const float*)d_in[11];
    const float* bo = (const float*)d_in[12];
    const float* W1 = (const float*)d_in[13];
    const float* b1 = (const float*)d_in[14];
    const float* W2 = (const float*)d_in[15];
    float* out = (float*)d_out;

    prep_kernel<<<512, 128>>>(ref_pts, W1, b1, W2, Wo);

    qkv_gemm_kernel<<<dim3(37, 4), 256>>>(raw_query, query_pos, raw_src, src_pos,
                                          Wq, bq, Wk, bk, Wv, bv);

    score_kernel<<<dim3(16, 38), 256>>>();

    softmax_kernel<<<300, 256>>>();

    pv_kernel<<<dim3(4, 38), 128>>>();

    outproj_kernel<<<dim3(4, 38), 128>>>(bo, out);
}

// round 5
// speedup vs baseline: 1.5343x; 1.1308x over previous
#include <cuda_runtime.h>

#define NQ 300
#define CC 256
#define NH 8
#define HD 32
#define HW 1024
#define HID 512

typedef unsigned long long ull;

// ---------------- packed f32x2 helpers (sm_103a) ----------------
__device__ __forceinline__ ull pk2(float lo, float hi) {
    ull r; asm("mov.b64 %0,{%1,%2};" : "=l"(r) : "f"(lo), "f"(hi)); return r;
}
__device__ __forceinline__ void upk2(ull v, float& lo, float& hi) {
    asm("mov.b64 {%0,%1},%2;" : "=f"(lo), "=f"(hi) : "l"(v));
}
__device__ __forceinline__ ull add2(ull a, ull b) {
    ull r; asm("add.rn.f32x2 %0,%1,%2;" : "=l"(r) : "l"(a), "l"(b)); return r;
}
__device__ __forceinline__ ull mul2(ull a, ull b) {
    ull r; asm("mul.rn.f32x2 %0,%1,%2;" : "=l"(r) : "l"(a), "l"(b)); return r;
}
__device__ __forceinline__ void fma2(ull& d, ull a, ull b) {
    asm("fma.rn.f32x2 %0,%1,%2,%0;" : "+l"(d) : "l"(a), "l"(b));
}

// ---------------- scratch (device globals; no allocation) ----------------
__device__ float g_q[NQ * CC];
__device__ float g_k[HW * CC];
__device__ float g_v[HW * CC];
__device__ float g_s[HID * NQ];       // s[f][q] = W1[f]·ref[q] + b1[f]
__device__ float g_t[HID * HW];       // NEGATED: -(W1[f]·key_pos[k])
__device__ float g_w2p[HID * 16];     // W2 splatted pairs: [f][h] -> (w2,w2), natural h order
__device__ float g_wot[CC * CC];      // Wo transposed: [c][n]
__device__ float g_S[NQ * NH * HW];   // scores -> (in-place) softmax probs, layout [q][h][k]
__device__ float g_ctx[NQ * CC];      // attention context

// ---------------- prep: s/t tables, W2 splat, Wo transpose ----------------
__global__ void __launch_bounds__(128) prep_kernel(const float* __restrict__ ref,
                                                   const float* __restrict__ W1,
                                                   const float* __restrict__ b1,
                                                   const float* __restrict__ W2,
                                                   const float* __restrict__ Wo) {
    int f = blockIdx.x;
    int tid = threadIdx.x;
    float w1x = W1[2 * f], w1y = W1[2 * f + 1], bb = b1[f];
    for (int k = tid; k < HW; k += 128) {
        int kx = k & 31, ky = k >> 5;
        float px = (kx + 0.5f) * (1.0f / 32.0f);
        float py = (ky + 0.5f) * (1.0f / 32.0f);
        g_t[f * HW + k] = -(w1x * px + w1y * py);
    }
    for (int q = tid; q < NQ; q += 128) {
        g_s[f * NQ + q] = w1x * ref[2 * q] + w1y * ref[2 * q + 1] + bb;
    }
    if (tid < NH) {
        float w = W2[tid * HID + f];
        g_w2p[f * 16 + 2 * tid] = w;
        g_w2p[f * 16 + 2 * tid + 1] = w;
    }
    int idx = blockIdx.x * 128 + tid;
    int r = idx >> 8, c = idx & 255;
    g_wot[c * 256 + r] = Wo[idx];
}

// ---------------- fused QKV projections (passing, unchanged) ----------------
__global__ void __launch_bounds__(256) qkv_gemm_kernel(const float* __restrict__ rq,
                                                       const float* __restrict__ qp,
                                                       const float* __restrict__ rs,
                                                       const float* __restrict__ sp,
                                                       const float* __restrict__ Wq,
                                                       const float* __restrict__ bq,
                                                       const float* __restrict__ Wk,
                                                       const float* __restrict__ bk,
                                                       const float* __restrict__ Wv,
                                                       const float* __restrict__ bv) {
    __shared__ float As[16][68];
    __shared__ float Bs[16][68];

    int mt = blockIdx.x;
    int n0 = blockIdx.y * 64;

    const float *A1, *A2, *W, *bias;
    float* out;
    int M, m0;
    if (mt < 5)       { A1 = rq; A2 = qp; W = Wq; bias = bq; out = g_q; M = NQ; m0 = mt * 64; }
    else if (mt < 21) { A1 = rs; A2 = sp; W = Wk; bias = bk; out = g_k; M = HW; m0 = (mt - 5) * 64; }
    else              { A1 = rs; A2 = sp; W = Wv; bias = bv; out = g_v; M = HW; m0 = (mt - 21) * 64; }

    int t = threadIdx.x;
    int tx = t & 15, ty = t >> 4;
    int r = t >> 2, c4 = t & 3;

    ull acc2[4][2];
#pragma unroll
    for (int i = 0; i < 4; ++i) { acc2[i][0] = 0ull; acc2[i][1] = 0ull; }

    for (int kc = 0; kc < 256; kc += 16) {
        int gm = m0 + r;
        if (gm >= M) gm = M - 1;
        float4 a = *(const float4*)&A1[gm * 256 + kc + c4 * 4];
        float4 a2 = *(const float4*)&A2[gm * 256 + kc + c4 * 4];
        a.x += a2.x; a.y += a2.y; a.z += a2.z; a.w += a2.w;
        As[c4 * 4 + 0][r] = a.x;
        As[c4 * 4 + 1][r] = a.y;
        As[c4 * 4 + 2][r] = a.z;
        As[c4 * 4 + 3][r] = a.w;

        float4 b = *(const float4*)&W[(n0 + r) * 256 + kc + c4 * 4];
        Bs[c4 * 4 + 0][r] = b.x;
        Bs[c4 * 4 + 1][r] = b.y;
        Bs[c4 * 4 + 2][r] = b.z;
        Bs[c4 * 4 + 3][r] = b.w;
        __syncthreads();

#pragma unroll
        for (int kk = 0; kk < 16; ++kk) {
            float4 av = *(const float4*)&As[kk][ty * 4];
            ulonglong2 bp = *(const ulonglong2*)&Bs[kk][tx * 4];
            ull a0 = pk2(av.x, av.x), a1 = pk2(av.y, av.y);
            ull a2p = pk2(av.z, av.z), a3 = pk2(av.w, av.w);
            fma2(acc2[0][0], a0, bp.x); fma2(acc2[0][1], a0, bp.y);
            fma2(acc2[1][0], a1, bp.x); fma2(acc2[1][1], a1, bp.y);
            fma2(acc2[2][0], a2p, bp.x); fma2(acc2[2][1], a2p, bp.y);
            fma2(acc2[3][0], a3, bp.x); fma2(acc2[3][1], a3, bp.y);
        }
        __syncthreads();
    }

    float4 b4 = *(const float4*)&bias[n0 + tx * 4];
#pragma unroll
    for (int i = 0; i < 4; ++i) {
        int gm = m0 + ty * 4 + i;
        if (gm < M) {
            float4 o;
            upk2(acc2[i][0], o.x, o.y);
            upk2(acc2[i][1], o.z, o.w);
            o.x += b4.x; o.y += b4.y; o.z += b4.z; o.w += b4.w;
            *(float4*)&out[gm * 256 + n0 + tx * 4] = o;
        }
    }
}

// ---------------- score v2: tile 8q x 128k, thread = (q, 4 keys) x all 8 heads ----------------
// grid (8 ktiles, 38 qtiles) = 304 blocks; 256 threads.
// acc[h][p]: h=head, p=keypair (keys kg*4+2p, +1). 16 ull accumulators.
__global__ void __launch_bounds__(256) score_kernel() {
    __shared__ float sm_q[512];    // phase1: [8q][64d]   phase2: [64f][8q]
    __shared__ float sm_k[8192];   // phase1: [64d][128k] phase2: [64f][128k]
    __shared__ float sm_w[1024];   // phase2: [64f][16] pair-splats h0..h7

    int k0 = blockIdx.x * 128;
    int q0 = blockIdx.y * 8;
    int t = threadIdx.x;
    int q = t >> 5;    // 0..7 (warp-uniform)
    int kg = t & 31;   // keys kg*4 .. kg*4+3

    ull acc[8][2];
#pragma unroll
    for (int h = 0; h < 8; ++h) { acc[h][0] = 0ull; acc[h][1] = 0ull; }

    // ===== phase 1: logits =====
#pragma unroll
    for (int c = 0; c < 4; ++c) {
        // stage q rows: [8q][64d], row-major
        if (t < 128) {
            int qr = t >> 4, d4 = t & 15;
            int gq = q0 + qr; if (gq > NQ - 1) gq = NQ - 1;
            *(float4*)&sm_q[qr * 64 + d4 * 4] =
                *(const float4*)&g_q[gq * 256 + c * 64 + d4 * 4];
        }
        // stage k transposed: [64d][128k]; store lanes contiguous in k (conflict-free)
#pragma unroll
        for (int j = 0; j < 8; ++j) {
            int idx = t + j * 256;
            int d4 = idx >> 7, kr = idx & 127;
            float4 b = *(const float4*)&g_k[(k0 + kr) * 256 + c * 64 + d4 * 4];
            sm_k[(d4 * 4 + 0) * 128 + kr] = b.x;
            sm_k[(d4 * 4 + 1) * 128 + kr] = b.y;
            sm_k[(d4 * 4 + 2) * 128 + kr] = b.z;
            sm_k[(d4 * 4 + 3) * 128 + kr] = b.w;
        }
        __syncthreads();

        // d 0..31 -> head 2c ; d 32..63 -> head 2c+1
#pragma unroll
        for (int half = 0; half < 2; ++half) {
#pragma unroll
            for (int dq = 0; dq < 8; ++dq) {
                float4 qv = *(const float4*)&sm_q[q * 64 + half * 32 + dq * 4];
                float qa[4] = {qv.x, qv.y, qv.z, qv.w};
#pragma unroll
                for (int i = 0; i < 4; ++i) {
                    int d = half * 32 + dq * 4 + i;
                    ulonglong2 kp = *(const ulonglong2*)&sm_k[d * 128 + kg * 4];
                    ull qq = pk2(qa[i], qa[i]);
                    fma2(acc[c * 2 + half][0], qq, kp.x);
                    fma2(acc[c * 2 + half][1], qq, kp.y);
                }
            }
        }
        __syncthreads();
    }

    {
        const float scale = 0.17677669529663688f; // 32^-0.5
        ull sc = pk2(scale, scale);
#pragma unroll
        for (int h = 0; h < 8; ++h) {
            acc[h][0] = mul2(acc[h][0], sc);
            acc[h][1] = mul2(acc[h][1], sc);
        }
    }

    // ===== phase 2: CPB bias =====
    for (int fc = 0; fc < 8; ++fc) {
        int f0 = fc * 64;
        // stage s: [64f][8q]
#pragma unroll
        for (int j = 0; j < 2; ++j) {
            int idx = t + j * 256;
            int fr = idx >> 3, ql = idx & 7;
            int gq = q0 + ql; if (gq > NQ - 1) gq = NQ - 1;
            sm_q[fr * 8 + ql] = g_s[(f0 + fr) * NQ + gq];
        }
        // stage t (negated): [64f][128k], direct float4 copy (g_t is [f][k])
#pragma unroll
        for (int j = 0; j < 8; ++j) {
            int idx = t + j * 256;
            int fr = idx >> 5, kq = idx & 31;
            *(float4*)&sm_k[fr * 128 + kq * 4] =
                *(const float4*)&g_t[(f0 + fr) * HW + k0 + kq * 4];
        }
        // stage w pair-splats: [64f][16]
        {
            int fr = t >> 2, part = t & 3;
            *(float4*)&sm_w[fr * 16 + part * 4] =
                *(const float4*)&g_w2p[(f0 + fr) * 16 + part * 4];
        }
        __syncthreads();

#pragma unroll 2
        for (int fl = 0; fl < 64; ++fl) {
            float sv = sm_q[fl * 8 + q];
            ull svv = pk2(sv, sv);
            ulonglong2 tp = *(const ulonglong2*)&sm_k[fl * 128 + kg * 4];
            ull xa = add2(svv, tp.x);
            ull xb = add2(svv, tp.y);
            float a0, a1, b0, b1;
            upk2(xa, a0, a1);
            upk2(xb, b0, b1);
            xa = pk2(fmaxf(a0, 0.0f), fmaxf(a1, 0.0f));
            xb = pk2(fmaxf(b0, 0.0f), fmaxf(b1, 0.0f));
            ulonglong2 w01 = *(const ulonglong2*)&sm_w[fl * 16 + 0];
            ulonglong2 w23 = *(const ulonglong2*)&sm_w[fl * 16 + 4];
            ulonglong2 w45 = *(const ulonglong2*)&sm_w[fl * 16 + 8];
            ulonglong2 w67 = *(const ulonglong2*)&sm_w[fl * 16 + 12];
            fma2(acc[0][0], xa, w01.x); fma2(acc[0][1], xb, w01.x);
            fma2(acc[1][0], xa, w01.y); fma2(acc[1][1], xb, w01.y);
            fma2(acc[2][0], xa, w23.x); fma2(acc[2][1], xb, w23.x);
            fma2(acc[3][0], xa, w23.y); fma2(acc[3][1], xb, w23.y);
            fma2(acc[4][0], xa, w45.x); fma2(acc[4][1], xb, w45.x);
            fma2(acc[5][0], xa, w45.y); fma2(acc[5][1], xb, w45.y);
            fma2(acc[6][0], xa, w67.x); fma2(acc[6][1], xb, w67.x);
            fma2(acc[7][0], xa, w67.y); fma2(acc[7][1], xb, w67.y);
        }
        __syncthreads();
    }

    // ===== store: float4 per (q,h), keys kg*4..+3 =====
    int gq = q0 + q;
    if (gq < NQ) {
#pragma unroll
        for (int h = 0; h < 8; ++h) {
            float4 o;
            upk2(acc[h][0], o.x, o.y);
            upk2(acc[h][1], o.z, o.w);
            *(float4*)&g_S[(gq * 8 + h) * HW + k0 + kg * 4] = o;
        }
    }
}

// ---------------- softmax: in-place on g_S. grid=300 (one query), warp=head ----------------
__global__ void __launch_bounds__(256) softmax_kernel() {
    int q = blockIdx.x;
    int warp = threadIdx.x >> 5, lane = threadIdx.x & 31;
    float4* rp = (float4*)&g_S[(q * 8 + warp) * 1024];

    float4 r[8];
#pragma unroll
    for (int j = 0; j < 8; ++j) r[j] = rp[lane + 32 * j];

    float m = -1e30f;
#pragma unroll
    for (int j = 0; j < 8; ++j) {
        m = fmaxf(m, fmaxf(fmaxf(r[j].x, r[j].y), fmaxf(r[j].z, r[j].w)));
    }
#pragma unroll
    for (int o = 16; o; o >>= 1) m = fmaxf(m, __shfl_xor_sync(0xffffffffu, m, o));

    float s = 0.0f;
#pragma unroll
    for (int j = 0; j < 8; ++j) {
        r[j].x = __expf(r[j].x - m); s += r[j].x;
        r[j].y = __expf(r[j].y - m); s += r[j].y;
        r[j].z = __expf(r[j].z - m); s += r[j].z;
        r[j].w = __expf(r[j].w - m); s += r[j].w;
    }
#pragma unroll
    for (int o = 16; o; o >>= 1) s += __shfl_xor_sync(0xffffffffu, s, o);
    float inv = 1.0f / s;

#pragma unroll
    for (int j = 0; j < 8; ++j) {
        r[j].x *= inv; r[j].y *= inv; r[j].z *= inv; r[j].w *= inv;
        rp[lane + 32 * j] = r[j];
    }
}

// ---------------- PV GEMM (passing, unchanged) ----------------
__global__ void __launch_bounds__(128) pv_kernel() {
    __shared__ float Psm[16 * 64];
    __shared__ float vsm[64 * 64];

    int by = blockIdx.x;
    int q0 = blockIdx.y * 8;
    int t = threadIdx.x;
    int qg = t >> 5;
    int cp = t & 31;
    int h = cp >> 4;
    int cpl = cp & 15;

    ull acc2[2] = {0ull, 0ull};

    for (int kc = 0; kc < 1024; kc += 64) {
#pragma unroll
        for (int it = 0; it < 2; ++it) {
            int idx = t + it * 128;
            int row = idx >> 4, kk4 = idx & 15;
            int q_l = row & 7, hh = row >> 3;
            int gq = q0 + q_l; if (gq > NQ - 1) gq = NQ - 1;
            *(float4*)&Psm[(hh * 8 + q_l) * 64 + kk4 * 4] =
                *(const float4*)&g_S[(gq * 8 + 2 * by + hh) * 1024 + kc + kk4 * 4];
        }
#pragma unroll
        for (int it = 0; it < 8; ++it) {
            int idx = t + it * 128;
            int row = idx >> 4, c4 = idx & 15;
            *(float4*)&vsm[row * 64 + c4 * 4] =
                *(const float4*)&g_v[(kc + row) * 256 + by * 64 + c4 * 4];
        }
        __syncthreads();

#pragma unroll 4
        for (int kk = 0; kk < 64; kk += 4) {
            float4 p0 = *(const float4*)&Psm[(h * 8 + qg * 2 + 0) * 64 + kk];
            float4 p1 = *(const float4*)&Psm[(h * 8 + qg * 2 + 1) * 64 + kk];
            float p0a[4] = {p0.x, p0.y, p0.z, p0.w};
            float p1a[4] = {p1.x, p1.y, p1.z, p1.w};
#pragma unroll
            for (int j = 0; j < 4; ++j) {
                ull vv = *(const ull*)&vsm[(kk + j) * 64 + h * 32 + cpl * 2];
                fma2(acc2[0], pk2(p0a[j], p0a[j]), vv);
                fma2(acc2[1], pk2(p1a[j], p1a[j]), vv);
            }
        }
        __syncthreads();
    }

#pragma unroll
    for (int i = 0; i < 2; ++i) {
        int gq = q0 + qg * 2 + i;
        if (gq < NQ) {
            float lo, hi;
            upk2(acc2[i], lo, hi);
            float2 o = {lo, hi};
            *(float2*)&g_ctx[gq * 256 + by * 64 + h * 32 + cpl * 2] = o;
        }
    }
}

// ---------------- out-proj GEMM (passing, unchanged) ----------------
__global__ void __launch_bounds__(128) outproj_kernel(const float* __restrict__ bo,
                                                      float* __restrict__ out) {
    __shared__ float Csm[8 * 64];
    __shared__ float wsm[64 * 64];

    int by = blockIdx.x;
    int q0 = blockIdx.y * 8;
    int t = threadIdx.x;
    int qg = t >> 5;
    int cp = t & 31;

    ull acc2[2] = {0ull, 0ull};

    for (int kc = 0; kc < 256; kc += 64) {
        {
            int row = t >> 4, kk4 = t & 15;
            int gq = q0 + row; if (gq > NQ - 1) gq = NQ - 1;
            *(float4*)&Csm[row * 64 + kk4 * 4] =
                *(const float4*)&g_ctx[gq * 256 + kc + kk4 * 4];
        }
#pragma unroll
        for (int it = 0; it < 8; ++it) {
            int idx = t + it * 128;
            int row = idx >> 4, c4 = idx & 15;
            *(float4*)&wsm[row * 64 + c4 * 4] =
                *(const float4*)&g_wot[(kc + row) * 256 + by * 64 + c4 * 4];
        }
        __syncthreads();

#pragma unroll 4
        for (int kk = 0; kk < 64; kk += 4) {
            float4 c0 = *(const float4*)&Csm[(qg * 2 + 0) * 64 + kk];
            float4 c1 = *(const float4*)&Csm[(qg * 2 + 1) * 64 + kk];
            float c0a[4] = {c0.x, c0.y, c0.z, c0.w};
            float c1a[4] = {c1.x, c1.y, c1.z, c1.w};
#pragma unroll
            for (int j = 0; j < 4; ++j) {
                ull ww = *(const ull*)&wsm[(kk + j) * 64 + cp * 2];
                fma2(acc2[0], pk2(c0a[j], c0a[j]), ww);
                fma2(acc2[1], pk2(c1a[j], c1a[j]), ww);
            }
        }
        __syncthreads();
    }

    float b0 = bo[by * 64 + cp * 2], b1 = bo[by * 64 + cp * 2 + 1];
#pragma unroll
    for (int i = 0; i < 2; ++i) {
        int gq = q0 + qg * 2 + i;
        if (gq < NQ) {
            float lo, hi;
            upk2(acc2[i], lo, hi);
            float2 o = {lo + b0, hi + b1};
            *(float2*)&out[gq * 256 + cp * 2 + by * 64] = o;
        }
    }
}

// ---------------- launch ----------------
extern "C" void kernel_launch(void* const* d_in, const int* in_sizes, int n_in,
                              void* d_out, int out_size) {
    const float* raw_query = (const float*)d_in[0];
    const float* query_pos = (const float*)d_in[1];
    const float* ref_pts   = (const float*)d_in[2];
    const float* raw_src   = (const float*)d_in[3];
    const float* src_pos   = (const float*)d_in[4];
    const float* Wq = (const float*)d_in[5];
    const float* bq = (const float*)d_in[6];
    const float* Wk = (const float*)d_in[7];
    const float* bk = (const float*)d_in[8];
    const float* Wv = (const float*)d_in[9];
    const float* bv = (const float*)d_in[10];
    const float* Wo = (const float*)d_in[11];
    const float* bo = (const float*)d_in[12];
    const float* W1 = (const float*)d_in[13];
    const float* b1 = (const float*)d_in[14];
    const float* W2 = (const float*)d_in[15];
    float* out = (float*)d_out;

    prep_kernel<<<512, 128>>>(ref_pts, W1, b1, W2, Wo);

    qkv_gemm_kernel<<<dim3(37, 4), 256>>>(raw_query, query_pos, raw_src, src_pos,
                                          Wq, bq, Wk, bk, Wv, bv);

    score_kernel<<<dim3(8, 38), 256>>>();

    softmax_kernel<<<300, 256>>>();

    pv_kernel<<<dim3(4, 38), 128>>>();

    outproj_kernel<<<dim3(4, 38), 128>>>(bo, out);
}

// round 6
// speedup vs baseline: 1.6315x; 1.0633x over previous
#include <cuda_runtime.h>

#define NQ 300
#define CC 256
#define NH 8
#define HD 32
#define HW 1024
#define HID 512

typedef unsigned long long ull;

// ---------------- packed f32x2 helpers (sm_103a) ----------------
__device__ __forceinline__ ull pk2(float lo, float hi) {
    ull r; asm("mov.b64 %0,{%1,%2};" : "=l"(r) : "f"(lo), "f"(hi)); return r;
}
__device__ __forceinline__ void upk2(ull v, float& lo, float& hi) {
    asm("mov.b64 {%0,%1},%2;" : "=f"(lo), "=f"(hi) : "l"(v));
}
__device__ __forceinline__ ull add2(ull a, ull b) {
    ull r; asm("add.rn.f32x2 %0,%1,%2;" : "=l"(r) : "l"(a), "l"(b)); return r;
}
__device__ __forceinline__ ull mul2(ull a, ull b) {
    ull r; asm("mul.rn.f32x2 %0,%1,%2;" : "=l"(r) : "l"(a), "l"(b)); return r;
}
__device__ __forceinline__ void fma2(ull& d, ull a, ull b) {
    asm("fma.rn.f32x2 %0,%1,%2,%0;" : "+l"(d) : "l"(a), "l"(b));
}

// ---------------- scratch (device globals; no allocation) ----------------
__device__ float g_q[NQ * CC];
__device__ float g_k[HW * CC];
__device__ float g_v[HW * CC];
__device__ float g_s[HID * NQ];       // s[f][q] = W1[f]·ref[q] + b1[f]
__device__ float g_t[HID * HW];       // NEGATED: -(W1[f]·key_pos[k])
__device__ float g_w2p[HID * 16];     // W2 splatted pairs: [f][h] -> (w2,w2), natural h order
__device__ float g_wot[CC * CC];      // Wo transposed: [c][n]
__device__ float g_S[NQ * NH * HW];   // logits -> (softmax) probs, layout [q][h][k]
__device__ float g_B[NQ * NH * HW];   // CPB bias, layout [q][h][k]
__device__ float g_ctx[NQ * CC];      // attention context

// ---------------- prep: s/t tables, W2 splat, Wo transpose ----------------
__global__ void __launch_bounds__(128) prep_kernel(const float* __restrict__ ref,
                                                   const float* __restrict__ W1,
                                                   const float* __restrict__ b1,
                                                   const float* __restrict__ W2,
                                                   const float* __restrict__ Wo) {
    int f = blockIdx.x;
    int tid = threadIdx.x;
    float w1x = W1[2 * f], w1y = W1[2 * f + 1], bb = b1[f];
    for (int k = tid; k < HW; k += 128) {
        int kx = k & 31, ky = k >> 5;
        float px = (kx + 0.5f) * (1.0f / 32.0f);
        float py = (ky + 0.5f) * (1.0f / 32.0f);
        g_t[f * HW + k] = -(w1x * px + w1y * py);
    }
    for (int q = tid; q < NQ; q += 128) {
        g_s[f * NQ + q] = w1x * ref[2 * q] + w1y * ref[2 * q + 1] + bb;
    }
    if (tid < NH) {
        float w = W2[tid * HID + f];
        g_w2p[f * 16 + 2 * tid] = w;
        g_w2p[f * 16 + 2 * tid + 1] = w;
    }
    int idx = blockIdx.x * 128 + tid;
    int r = idx >> 8, c = idx & 255;
    g_wot[c * 256 + r] = Wo[idx];
}

// ---------------- fused QKV projections (passing, unchanged) ----------------
__global__ void __launch_bounds__(256) qkv_gemm_kernel(const float* __restrict__ rq,
                                                       const float* __restrict__ qp,
                                                       const float* __restrict__ rs,
                                                       const float* __restrict__ sp,
                                                       const float* __restrict__ Wq,
                                                       const float* __restrict__ bq,
                                                       const float* __restrict__ Wk,
                                                       const float* __restrict__ bk,
                                                       const float* __restrict__ Wv,
                                                       const float* __restrict__ bv) {
    __shared__ float As[16][68];
    __shared__ float Bs[16][68];

    int mt = blockIdx.x;
    int n0 = blockIdx.y * 64;

    const float *A1, *A2, *W, *bias;
    float* out;
    int M, m0;
    if (mt < 5)       { A1 = rq; A2 = qp; W = Wq; bias = bq; out = g_q; M = NQ; m0 = mt * 64; }
    else if (mt < 21) { A1 = rs; A2 = sp; W = Wk; bias = bk; out = g_k; M = HW; m0 = (mt - 5) * 64; }
    else              { A1 = rs; A2 = sp; W = Wv; bias = bv; out = g_v; M = HW; m0 = (mt - 21) * 64; }

    int t = threadIdx.x;
    int tx = t & 15, ty = t >> 4;
    int r = t >> 2, c4 = t & 3;

    ull acc2[4][2];
#pragma unroll
    for (int i = 0; i < 4; ++i) { acc2[i][0] = 0ull; acc2[i][1] = 0ull; }

    for (int kc = 0; kc < 256; kc += 16) {
        int gm = m0 + r;
        if (gm >= M) gm = M - 1;
        float4 a = *(const float4*)&A1[gm * 256 + kc + c4 * 4];
        float4 a2 = *(const float4*)&A2[gm * 256 + kc + c4 * 4];
        a.x += a2.x; a.y += a2.y; a.z += a2.z; a.w += a2.w;
        As[c4 * 4 + 0][r] = a.x;
        As[c4 * 4 + 1][r] = a.y;
        As[c4 * 4 + 2][r] = a.z;
        As[c4 * 4 + 3][r] = a.w;

        float4 b = *(const float4*)&W[(n0 + r) * 256 + kc + c4 * 4];
        Bs[c4 * 4 + 0][r] = b.x;
        Bs[c4 * 4 + 1][r] = b.y;
        Bs[c4 * 4 + 2][r] = b.z;
        Bs[c4 * 4 + 3][r] = b.w;
        __syncthreads();

#pragma unroll
        for (int kk = 0; kk < 16; ++kk) {
            float4 av = *(const float4*)&As[kk][ty * 4];
            ulonglong2 bp = *(const ulonglong2*)&Bs[kk][tx * 4];
            ull a0 = pk2(av.x, av.x), a1 = pk2(av.y, av.y);
            ull a2p = pk2(av.z, av.z), a3 = pk2(av.w, av.w);
            fma2(acc2[0][0], a0, bp.x); fma2(acc2[0][1], a0, bp.y);
            fma2(acc2[1][0], a1, bp.x); fma2(acc2[1][1], a1, bp.y);
            fma2(acc2[2][0], a2p, bp.x); fma2(acc2[2][1], a2p, bp.y);
            fma2(acc2[3][0], a3, bp.x); fma2(acc2[3][1], a3, bp.y);
        }
        __syncthreads();
    }

    float4 b4 = *(const float4*)&bias[n0 + tx * 4];
#pragma unroll
    for (int i = 0; i < 4; ++i) {
        int gm = m0 + ty * 4 + i;
        if (gm < M) {
            float4 o;
            upk2(acc2[i][0], o.x, o.y);
            upk2(acc2[i][1], o.z, o.w);
            o.x += b4.x; o.y += b4.y; o.z += b4.z; o.w += b4.w;
            *(float4*)&out[gm * 256 + n0 + tx * 4] = o;
        }
    }
}

// ---------------- logits: g_S = scale * q.k  (8q x 64k tiles, 128 thr) ----------------
// grid (16 kt, 38 qt) = 608 blocks. thread: qp = t>>5 (2 queries), kg = t&31 (2 keys).
__global__ void __launch_bounds__(128) logits_kernel() {
    __shared__ float sm_qT[64 * 8];   // [64d][8q]
    __shared__ float sm_kT[64 * 64];  // [64d][64k]

    int k0 = blockIdx.x * 64;
    int q0 = blockIdx.y * 8;
    int t = threadIdx.x;
    int qp = t >> 5;   // 0..3 -> queries q0+2qp, +1
    int kg = t & 31;   // keys k0+2kg, +1

    ull acc[2][8];
#pragma unroll
    for (int i = 0; i < 2; ++i)
#pragma unroll
        for (int h = 0; h < 8; ++h) acc[i][h] = 0ull;

#pragma unroll
    for (int c = 0; c < 4; ++c) {
        // stage qT: [64d][8q]
#pragma unroll
        for (int j = 0; j < 4; ++j) {
            int idx = t + j * 128;
            int d = idx >> 3, ql = idx & 7;
            int gq = q0 + ql; if (gq > NQ - 1) gq = NQ - 1;
            sm_qT[d * 8 + ql] = g_q[gq * 256 + c * 64 + d];
        }
        // stage kT: [64d][64k]
#pragma unroll
        for (int j = 0; j < 8; ++j) {
            int idx = t + j * 128;
            int d4 = idx >> 6, kr = idx & 63;
            float4 b = *(const float4*)&g_k[(k0 + kr) * 256 + c * 64 + d4 * 4];
            sm_kT[(d4 * 4 + 0) * 64 + kr] = b.x;
            sm_kT[(d4 * 4 + 1) * 64 + kr] = b.y;
            sm_kT[(d4 * 4 + 2) * 64 + kr] = b.z;
            sm_kT[(d4 * 4 + 3) * 64 + kr] = b.w;
        }
        __syncthreads();

#pragma unroll
        for (int half = 0; half < 2; ++half) {
            int h = c * 2 + half;
#pragma unroll 8
            for (int dl = 0; dl < 32; ++dl) {
                int d = half * 32 + dl;
                ull sv2 = *(const ull*)&sm_qT[d * 8 + qp * 2];
                float s0, s1; upk2(sv2, s0, s1);
                ull kp = *(const ull*)&sm_kT[d * 64 + kg * 2];
                fma2(acc[0][h], pk2(s0, s0), kp);
                fma2(acc[1][h], pk2(s1, s1), kp);
            }
        }
        __syncthreads();
    }

    const float scale = 0.17677669529663688f; // 32^-0.5
    ull sc = pk2(scale, scale);
#pragma unroll
    for (int i = 0; i < 2; ++i) {
        int gq = q0 + qp * 2 + i;
        if (gq < NQ) {
#pragma unroll
            for (int h = 0; h < 8; ++h) {
                ull v = mul2(acc[i][h], sc);
                float lo, hi; upk2(v, lo, hi);
                float2 o = {lo, hi};
                *(float2*)&g_S[(gq * 8 + h) * HW + k0 + kg * 2] = o;
            }
        }
    }
}

// ---------------- bias: g_B = sum_f relu(s-t) * W2  (8q x 64k tiles, 128 thr) ----------------
// grid (16 kt, 38 qt) = 608 blocks; thread: 2q x 2k x 8h = 16 FFMA2 accumulators.
__global__ void __launch_bounds__(128) bias_kernel() {
    __shared__ float sm_s[64 * 8];   // [64f][8q]
    __shared__ float sm_t[64 * 64];  // [64f][64k] (negated t)
    __shared__ float sm_w[64 * 16];  // [64f][16] pair-splats h0..h7

    int k0 = blockIdx.x * 64;
    int q0 = blockIdx.y * 8;
    int t = threadIdx.x;
    int qp = t >> 5;
    int kg = t & 31;

    ull acc[2][8];
#pragma unroll
    for (int i = 0; i < 2; ++i)
#pragma unroll
        for (int h = 0; h < 8; ++h) acc[i][h] = 0ull;

    for (int fc = 0; fc < 8; ++fc) {
        int f0 = fc * 64;
        // stage s: [64f][8q]
#pragma unroll
        for (int j = 0; j < 4; ++j) {
            int idx = t + j * 128;
            int fr = idx >> 3, ql = idx & 7;
            int gq = q0 + ql; if (gq > NQ - 1) gq = NQ - 1;
            sm_s[fr * 8 + ql] = g_s[(f0 + fr) * NQ + gq];
        }
        // stage t: [64f][64k] direct float4 copy
#pragma unroll
        for (int j = 0; j < 8; ++j) {
            int idx = t + j * 128;
            int fr = idx >> 4, k4 = idx & 15;
            *(float4*)&sm_t[fr * 64 + k4 * 4] =
                *(const float4*)&g_t[(f0 + fr) * HW + k0 + k4 * 4];
        }
        // stage w: [64f][16]
#pragma unroll
        for (int j = 0; j < 2; ++j) {
            int idx = t + j * 128;
            int fr = idx >> 2, part = idx & 3;
            *(float4*)&sm_w[fr * 16 + part * 4] =
                *(const float4*)&g_w2p[(f0 + fr) * 16 + part * 4];
        }
        __syncthreads();

#pragma unroll 4
        for (int fl = 0; fl < 64; ++fl) {
            ull sv2 = *(const ull*)&sm_s[fl * 8 + qp * 2];
            float s0, s1; upk2(sv2, s0, s1);
            ull tp = *(const ull*)&sm_t[fl * 64 + kg * 2];
            ull xa = add2(pk2(s0, s0), tp);
            ull xb = add2(pk2(s1, s1), tp);
            float a0, a1, b0, b1;
            upk2(xa, a0, a1); upk2(xb, b0, b1);
            xa = pk2(fmaxf(a0, 0.0f), fmaxf(a1, 0.0f));
            xb = pk2(fmaxf(b0, 0.0f), fmaxf(b1, 0.0f));
            ulonglong2 w01 = *(const ulonglong2*)&sm_w[fl * 16 + 0];
            ulonglong2 w23 = *(const ulonglong2*)&sm_w[fl * 16 + 4];
            ulonglong2 w45 = *(const ulonglong2*)&sm_w[fl * 16 + 8];
            ulonglong2 w67 = *(const ulonglong2*)&sm_w[fl * 16 + 12];
            fma2(acc[0][0], xa, w01.x); fma2(acc[1][0], xb, w01.x);
            fma2(acc[0][1], xa, w01.y); fma2(acc[1][1], xb, w01.y);
            fma2(acc[0][2], xa, w23.x); fma2(acc[1][2], xb, w23.x);
            fma2(acc[0][3], xa, w23.y); fma2(acc[1][3], xb, w23.y);
            fma2(acc[0][4], xa, w45.x); fma2(acc[1][4], xb, w45.x);
            fma2(acc[0][5], xa, w45.y); fma2(acc[1][5], xb, w45.y);
            fma2(acc[0][6], xa, w67.x); fma2(acc[1][6], xb, w67.x);
            fma2(acc[0][7], xa, w67.y); fma2(acc[1][7], xb, w67.y);
        }
        __syncthreads();
    }

#pragma unroll
    for (int i = 0; i < 2; ++i) {
        int gq = q0 + qp * 2 + i;
        if (gq < NQ) {
#pragma unroll
            for (int h = 0; h < 8; ++h) {
                float lo, hi; upk2(acc[i][h], lo, hi);
                float2 o = {lo, hi};
                *(float2*)&g_B[(gq * 8 + h) * HW + k0 + kg * 2] = o;
            }
        }
    }
}

// ---------------- softmax: probs = softmax(g_S + g_B), written to g_S ----------------
__global__ void __launch_bounds__(256) softmax_kernel() {
    int q = blockIdx.x;
    int warp = threadIdx.x >> 5, lane = threadIdx.x & 31;
    float4* rp = (float4*)&g_S[(q * 8 + warp) * 1024];
    const float4* bp = (const float4*)&g_B[(q * 8 + warp) * 1024];

    float4 r[8];
#pragma unroll
    for (int j = 0; j < 8; ++j) {
        float4 a = rp[lane + 32 * j];
        float4 b = bp[lane + 32 * j];
        r[j].x = a.x + b.x; r[j].y = a.y + b.y;
        r[j].z = a.z + b.z; r[j].w = a.w + b.w;
    }

    float m = -1e30f;
#pragma unroll
    for (int j = 0; j < 8; ++j) {
        m = fmaxf(m, fmaxf(fmaxf(r[j].x, r[j].y), fmaxf(r[j].z, r[j].w)));
    }
#pragma unroll
    for (int o = 16; o; o >>= 1) m = fmaxf(m, __shfl_xor_sync(0xffffffffu, m, o));

    float s = 0.0f;
#pragma unroll
    for (int j = 0; j < 8; ++j) {
        r[j].x = __expf(r[j].x - m); s += r[j].x;
        r[j].y = __expf(r[j].y - m); s += r[j].y;
        r[j].z = __expf(r[j].z - m); s += r[j].z;
        r[j].w = __expf(r[j].w - m); s += r[j].w;
    }
#pragma unroll
    for (int o = 16; o; o >>= 1) s += __shfl_xor_sync(0xffffffffu, s, o);
    float inv = 1.0f / s;

#pragma unroll
    for (int j = 0; j < 8; ++j) {
        r[j].x *= inv; r[j].y *= inv; r[j].z *= inv; r[j].w *= inv;
        rp[lane + 32 * j] = r[j];
    }
}

// ---------------- PV GEMM (passing, unchanged) ----------------
__global__ void __launch_bounds__(128) pv_kernel() {
    __shared__ float Psm[16 * 64];
    __shared__ float vsm[64 * 64];

    int by = blockIdx.x;
    int q0 = blockIdx.y * 8;
    int t = threadIdx.x;
    int qg = t >> 5;
    int cp = t & 31;
    int h = cp >> 4;
    int cpl = cp & 15;

    ull acc2[2] = {0ull, 0ull};

    for (int kc = 0; kc < 1024; kc += 64) {
#pragma unroll
        for (int it = 0; it < 2; ++it) {
            int idx = t + it * 128;
            int row = idx >> 4, kk4 = idx & 15;
            int q_l = row & 7, hh = row >> 3;
            int gq = q0 + q_l; if (gq > NQ - 1) gq = NQ - 1;
            *(float4*)&Psm[(hh * 8 + q_l) * 64 + kk4 * 4] =
                *(const float4*)&g_S[(gq * 8 + 2 * by + hh) * 1024 + kc + kk4 * 4];
        }
#pragma unroll
        for (int it = 0; it < 8; ++it) {
            int idx = t + it * 128;
            int row = idx >> 4, c4 = idx & 15;
            *(float4*)&vsm[row * 64 + c4 * 4] =
                *(const float4*)&g_v[(kc + row) * 256 + by * 64 + c4 * 4];
        }
        __syncthreads();

#pragma unroll 4
        for (int kk = 0; kk < 64; kk += 4) {
            float4 p0 = *(const float4*)&Psm[(h * 8 + qg * 2 + 0) * 64 + kk];
            float4 p1 = *(const float4*)&Psm[(h * 8 + qg * 2 + 1) * 64 + kk];
            float p0a[4] = {p0.x, p0.y, p0.z, p0.w};
            float p1a[4] = {p1.x, p1.y, p1.z, p1.w};
#pragma unroll
            for (int j = 0; j < 4; ++j) {
                ull vv = *(const ull*)&vsm[(kk + j) * 64 + h * 32 + cpl * 2];
                fma2(acc2[0], pk2(p0a[j], p0a[j]), vv);
                fma2(acc2[1], pk2(p1a[j], p1a[j]), vv);
            }
        }
        __syncthreads();
    }

#pragma unroll
    for (int i = 0; i < 2; ++i) {
        int gq = q0 + qg * 2 + i;
        if (gq < NQ) {
            float lo, hi;
            upk2(acc2[i], lo, hi);
            float2 o = {lo, hi};
            *(float2*)&g_ctx[gq * 256 + by * 64 + h * 32 + cpl * 2] = o;
        }
    }
}

// ---------------- out-proj GEMM (passing, unchanged) ----------------
__global__ void __launch_bounds__(128) outproj_kernel(const float* __restrict__ bo,
                                                      float* __restrict__ out) {
    __shared__ float Csm[8 * 64];
    __shared__ float wsm[64 * 64];

    int by = blockIdx.x;
    int q0 = blockIdx.y * 8;
    int t = threadIdx.x;
    int qg = t >> 5;
    int cp = t & 31;

    ull acc2[2] = {0ull, 0ull};

    for (int kc = 0; kc < 256; kc += 64) {
        {
            int row = t >> 4, kk4 = t & 15;
            int gq = q0 + row; if (gq > NQ - 1) gq = NQ - 1;
            *(float4*)&Csm[row * 64 + kk4 * 4] =
                *(const float4*)&g_ctx[gq * 256 + kc + kk4 * 4];
        }
#pragma unroll
        for (int it = 0; it < 8; ++it) {
            int idx = t + it * 128;
            int row = idx >> 4, c4 = idx & 15;
            *(float4*)&wsm[row * 64 + c4 * 4] =
                *(const float4*)&g_wot[(kc + row) * 256 + by * 64 + c4 * 4];
        }
        __syncthreads();

#pragma unroll 4
        for (int kk = 0; kk < 64; kk += 4) {
            float4 c0 = *(const float4*)&Csm[(qg * 2 + 0) * 64 + kk];
            float4 c1 = *(const float4*)&Csm[(qg * 2 + 1) * 64 + kk];
            float c0a[4] = {c0.x, c0.y, c0.z, c0.w};
            float c1a[4] = {c1.x, c1.y, c1.z, c1.w};
#pragma unroll
            for (int j = 0; j < 4; ++j) {
                ull ww = *(const ull*)&wsm[(kk + j) * 64 + cp * 2];
                fma2(acc2[0], pk2(c0a[j], c0a[j]), ww);
                fma2(acc2[1], pk2(c1a[j], c1a[j]), ww);
            }
        }
        __syncthreads();
    }

    float b0 = bo[by * 64 + cp * 2], b1 = bo[by * 64 + cp * 2 + 1];
#pragma unroll
    for (int i = 0; i < 2; ++i) {
        int gq = q0 + qg * 2 + i;
        if (gq < NQ) {
            float lo, hi;
            upk2(acc2[i], lo, hi);
            float2 o = {lo + b0, hi + b1};
            *(float2*)&out[gq * 256 + cp * 2 + by * 64] = o;
        }
    }
}

// ---------------- launch ----------------
extern "C" void kernel_launch(void* const* d_in, const int* in_sizes, int n_in,
                              void* d_out, int out_size) {
    const float* raw_query = (const float*)d_in[0];
    const float* query_pos = (const float*)d_in[1];
    const float* ref_pts   = (const float*)d_in[2];
    const float* raw_src   = (const float*)d_in[3];
    const float* src_pos   = (const float*)d_in[4];
    const float* Wq = (const float*)d_in[5];
    const float* bq = (const float*)d_in[6];
    const float* Wk = (const float*)d_in[7];
    const float* bk = (const float*)d_in[8];
    const float* Wv = (const float*)d_in[9];
    const float* bv = (const float*)d_in[10];
    const float* Wo = (const float*)d_in[11];
    const float* bo = (const float*)d_in[12];
    const float* W1 = (const float*)d_in[13];
    const float* b1 = (const float*)d_in[14];
    const float* W2 = (const float*)d_in[15];
    float* out = (float*)d_out;

    prep_kernel<<<512, 128>>>(ref_pts, W1, b1, W2, Wo);          // 1

    qkv_gemm_kernel<<<dim3(37, 4), 256>>>(raw_query, query_pos, raw_src, src_pos,
                                          Wq, bq, Wk, bk, Wv, bv); // 2

    logits_kernel<<<dim3(16, 38), 128>>>();                       // 3

    bias_kernel<<<dim3(16, 38), 128>>>();                         // 4 (ncu capture slot)

    softmax_kernel<<<300, 256>>>();                               // 5

    pv_kernel<<<dim3(4, 38), 128>>>();                            // 6

    outproj_kernel<<<dim3(4, 38), 128>>>(bo, out);                // 7
}

// round 7
// speedup vs baseline: 1.7342x; 1.0630x over previous
#include <cuda_runtime.h>

#define NQ 300
#define CC 256
#define NH 8
#define HD 32
#define HW 1024
#define HID 512

typedef unsigned long long ull;

// ---------------- packed f32x2 helpers (sm_103a) ----------------
__device__ __forceinline__ ull pk2(float lo, float hi) {
    ull r; asm("mov.b64 %0,{%1,%2};" : "=l"(r) : "f"(lo), "f"(hi)); return r;
}
__device__ __forceinline__ void upk2(ull v, float& lo, float& hi) {
    asm("mov.b64 {%0,%1},%2;" : "=f"(lo), "=f"(hi) : "l"(v));
}
__device__ __forceinline__ ull add2(ull a, ull b) {
    ull r; asm("add.rn.f32x2 %0,%1,%2;" : "=l"(r) : "l"(a), "l"(b)); return r;
}
__device__ __forceinline__ ull mul2(ull a, ull b) {
    ull r; asm("mul.rn.f32x2 %0,%1,%2;" : "=l"(r) : "l"(a), "l"(b)); return r;
}
__device__ __forceinline__ void fma2(ull& d, ull a, ull b) {
    asm("fma.rn.f32x2 %0,%1,%2,%0;" : "+l"(d) : "l"(a), "l"(b));
}

// ---------------- scratch (device globals; no allocation) ----------------
__device__ float g_q[NQ * CC];
__device__ float g_k[HW * CC];
__device__ float g_v[HW * CC];
__device__ float g_s[HID * NQ];       // s[f][q] = W1[f]·ref[q] + b1[f]
__device__ float g_t[HID * HW];       // NEGATED: -(W1[f]·key_pos[k])
__device__ float g_w2p[HID * 16];     // W2 splatted pairs: [f][h] -> (w2,w2)
__device__ float g_wot[CC * CC];      // Wo transposed: [c][n]
__device__ float g_S[NQ * NH * HW];   // logits -> (softmax) probs, layout [q][h][k]
__device__ float g_B[NQ * NH * HW];   // CPB bias, f 0..255
__device__ float g_B2[NQ * NH * HW];  // CPB bias, f 256..511
__device__ float g_ctx[NQ * CC];      // attention context

// ---------------- prep: s/t tables, W2 splat, Wo transpose ----------------
__global__ void __launch_bounds__(128) prep_kernel(const float* __restrict__ ref,
                                                   const float* __restrict__ W1,
                                                   const float* __restrict__ b1,
                                                   const float* __restrict__ W2,
                                                   const float* __restrict__ Wo) {
    int f = blockIdx.x;
    int tid = threadIdx.x;
    float w1x = W1[2 * f], w1y = W1[2 * f + 1], bb = b1[f];
    for (int k = tid; k < HW; k += 128) {
        int kx = k & 31, ky = k >> 5;
        float px = (kx + 0.5f) * (1.0f / 32.0f);
        float py = (ky + 0.5f) * (1.0f / 32.0f);
        g_t[f * HW + k] = -(w1x * px + w1y * py);
    }
    for (int q = tid; q < NQ; q += 128) {
        g_s[f * NQ + q] = w1x * ref[2 * q] + w1y * ref[2 * q + 1] + bb;
    }
    if (tid < NH) {
        float w = W2[tid * HID + f];
        g_w2p[f * 16 + 2 * tid] = w;
        g_w2p[f * 16 + 2 * tid + 1] = w;
    }
    int idx = blockIdx.x * 128 + tid;
    int r = idx >> 8, c = idx & 255;
    g_wot[c * 256 + r] = Wo[idx];
}

// ---------------- fused QKV projections (passing, unchanged) ----------------
__global__ void __launch_bounds__(256) qkv_gemm_kernel(const float* __restrict__ rq,
                                                       const float* __restrict__ qp,
                                                       const float* __restrict__ rs,
                                                       const float* __restrict__ sp,
                                                       const float* __restrict__ Wq,
                                                       const float* __restrict__ bq,
                                                       const float* __restrict__ Wk,
                                                       const float* __restrict__ bk,
                                                       const float* __restrict__ Wv,
                                                       const float* __restrict__ bv) {
    __shared__ float As[16][68];
    __shared__ float Bs[16][68];

    int mt = blockIdx.x;
    int n0 = blockIdx.y * 64;

    const float *A1, *A2, *W, *bias;
    float* out;
    int M, m0;
    if (mt < 5)       { A1 = rq; A2 = qp; W = Wq; bias = bq; out = g_q; M = NQ; m0 = mt * 64; }
    else if (mt < 21) { A1 = rs; A2 = sp; W = Wk; bias = bk; out = g_k; M = HW; m0 = (mt - 5) * 64; }
    else              { A1 = rs; A2 = sp; W = Wv; bias = bv; out = g_v; M = HW; m0 = (mt - 21) * 64; }

    int t = threadIdx.x;
    int tx = t & 15, ty = t >> 4;
    int r = t >> 2, c4 = t & 3;

    ull acc2[4][2];
#pragma unroll
    for (int i = 0; i < 4; ++i) { acc2[i][0] = 0ull; acc2[i][1] = 0ull; }

    for (int kc = 0; kc < 256; kc += 16) {
        int gm = m0 + r;
        if (gm >= M) gm = M - 1;
        float4 a = *(const float4*)&A1[gm * 256 + kc + c4 * 4];
        float4 a2 = *(const float4*)&A2[gm * 256 + kc + c4 * 4];
        a.x += a2.x; a.y += a2.y; a.z += a2.z; a.w += a2.w;
        As[c4 * 4 + 0][r] = a.x;
        As[c4 * 4 + 1][r] = a.y;
        As[c4 * 4 + 2][r] = a.z;
        As[c4 * 4 + 3][r] = a.w;

        float4 b = *(const float4*)&W[(n0 + r) * 256 + kc + c4 * 4];
        Bs[c4 * 4 + 0][r] = b.x;
        Bs[c4 * 4 + 1][r] = b.y;
        Bs[c4 * 4 + 2][r] = b.z;
        Bs[c4 * 4 + 3][r] = b.w;
        __syncthreads();

#pragma unroll
        for (int kk = 0; kk < 16; ++kk) {
            float4 av = *(const float4*)&As[kk][ty * 4];
            ulonglong2 bp = *(const ulonglong2*)&Bs[kk][tx * 4];
            ull a0 = pk2(av.x, av.x), a1 = pk2(av.y, av.y);
            ull a2p = pk2(av.z, av.z), a3 = pk2(av.w, av.w);
            fma2(acc2[0][0], a0, bp.x); fma2(acc2[0][1], a0, bp.y);
            fma2(acc2[1][0], a1, bp.x); fma2(acc2[1][1], a1, bp.y);
            fma2(acc2[2][0], a2p, bp.x); fma2(acc2[2][1], a2p, bp.y);
            fma2(acc2[3][0], a3, bp.x); fma2(acc2[3][1], a3, bp.y);
        }
        __syncthreads();
    }

    float4 b4 = *(const float4*)&bias[n0 + tx * 4];
#pragma unroll
    for (int i = 0; i < 4; ++i) {
        int gm = m0 + ty * 4 + i;
        if (gm < M) {
            float4 o;
            upk2(acc2[i][0], o.x, o.y);
            upk2(acc2[i][1], o.z, o.w);
            o.x += b4.x; o.y += b4.y; o.z += b4.z; o.w += b4.w;
            *(float4*)&out[gm * 256 + n0 + tx * 4] = o;
        }
    }
}

// ---------------- score2: merged logits + split bias ----------------
// grid (16 kt, 38 qt, 3): z=0 logits; z=1 bias f[0,256); z=2 bias f[256,512).
// 128 threads; tile 8q x 64k; thread: qp=t>>5 (2 q), kg=t&31 (2 keys), all 8 heads.
__global__ void __launch_bounds__(128) score2_kernel() {
    __shared__ float sm_a[64 * 8];   // qT / s : [64][8q]
    __shared__ float sm_b[64 * 64];  // kT / t : [64][64k]
    __shared__ float sm_w[64 * 16];  // w pair-splats (bias only)

    int k0 = blockIdx.x * 64;
    int q0 = blockIdx.y * 8;
    int z = blockIdx.z;
    int t = threadIdx.x;
    int qp = t >> 5;   // 2 queries: q0+2qp, +1
    int kg = t & 31;   // 2 keys: k0+2kg, +1

    ull acc[2][8];
#pragma unroll
    for (int i = 0; i < 2; ++i)
#pragma unroll
        for (int h = 0; h < 8; ++h) acc[i][h] = 0ull;

    if (z == 0) {
        // ===== logits =====
#pragma unroll
        for (int c = 0; c < 4; ++c) {
#pragma unroll
            for (int j = 0; j < 4; ++j) {
                int idx = t + j * 128;
                int d = idx >> 3, ql = idx & 7;
                int gq = q0 + ql; if (gq > NQ - 1) gq = NQ - 1;
                sm_a[d * 8 + ql] = g_q[gq * 256 + c * 64 + d];
            }
#pragma unroll
            for (int j = 0; j < 8; ++j) {
                int idx = t + j * 128;
                int d4 = idx >> 6, kr = idx & 63;
                float4 b = *(const float4*)&g_k[(k0 + kr) * 256 + c * 64 + d4 * 4];
                sm_b[(d4 * 4 + 0) * 64 + kr] = b.x;
                sm_b[(d4 * 4 + 1) * 64 + kr] = b.y;
                sm_b[(d4 * 4 + 2) * 64 + kr] = b.z;
                sm_b[(d4 * 4 + 3) * 64 + kr] = b.w;
            }
            __syncthreads();

#pragma unroll
            for (int half = 0; half < 2; ++half) {
                int h = c * 2 + half;
#pragma unroll 8
                for (int dl = 0; dl < 32; ++dl) {
                    int d = half * 32 + dl;
                    ull sv2 = *(const ull*)&sm_a[d * 8 + qp * 2];
                    float s0, s1; upk2(sv2, s0, s1);
                    ull kp = *(const ull*)&sm_b[d * 64 + kg * 2];
                    fma2(acc[0][h], pk2(s0, s0), kp);
                    fma2(acc[1][h], pk2(s1, s1), kp);
                }
            }
            __syncthreads();
        }

        const float scale = 0.17677669529663688f; // 32^-0.5
        ull sc = pk2(scale, scale);
#pragma unroll
        for (int i = 0; i < 2; ++i) {
            int gq = q0 + qp * 2 + i;
            if (gq < NQ) {
#pragma unroll
                for (int h = 0; h < 8; ++h) {
                    ull v = mul2(acc[i][h], sc);
                    float lo, hi; upk2(v, lo, hi);
                    float2 o = {lo, hi};
                    *(float2*)&g_S[(gq * 8 + h) * HW + k0 + kg * 2] = o;
                }
            }
        }
    } else {
        // ===== bias half: f in [fbase, fbase+256) =====
        int fbase = (z - 1) * 256;
        float* gB = (z == 1) ? g_B : g_B2;

        for (int fc = 0; fc < 4; ++fc) {
            int f0 = fbase + fc * 64;
#pragma unroll
            for (int j = 0; j < 4; ++j) {
                int idx = t + j * 128;
                int fr = idx >> 3, ql = idx & 7;
                int gq = q0 + ql; if (gq > NQ - 1) gq = NQ - 1;
                sm_a[fr * 8 + ql] = g_s[(f0 + fr) * NQ + gq];
            }
#pragma unroll
            for (int j = 0; j < 8; ++j) {
                int idx = t + j * 128;
                int fr = idx >> 4, k4 = idx & 15;
                *(float4*)&sm_b[fr * 64 + k4 * 4] =
                    *(const float4*)&g_t[(f0 + fr) * HW + k0 + k4 * 4];
            }
#pragma unroll
            for (int j = 0; j < 2; ++j) {
                int idx = t + j * 128;
                int fr = idx >> 2, part = idx & 3;
                *(float4*)&sm_w[fr * 16 + part * 4] =
                    *(const float4*)&g_w2p[(f0 + fr) * 16 + part * 4];
            }
            __syncthreads();

#pragma unroll 8
            for (int fl = 0; fl < 64; ++fl) {
                ull sv2 = *(const ull*)&sm_a[fl * 8 + qp * 2];
                float s0, s1; upk2(sv2, s0, s1);
                ull tp = *(const ull*)&sm_b[fl * 64 + kg * 2];
                ull xa = add2(pk2(s0, s0), tp);
                ull xb = add2(pk2(s1, s1), tp);
                float a0, a1, b0, b1;
                upk2(xa, a0, a1); upk2(xb, b0, b1);
                xa = pk2(fmaxf(a0, 0.0f), fmaxf(a1, 0.0f));
                xb = pk2(fmaxf(b0, 0.0f), fmaxf(b1, 0.0f));
                ulonglong2 w01 = *(const ulonglong2*)&sm_w[fl * 16 + 0];
                ulonglong2 w23 = *(const ulonglong2*)&sm_w[fl * 16 + 4];
                ulonglong2 w45 = *(const ulonglong2*)&sm_w[fl * 16 + 8];
                ulonglong2 w67 = *(const ulonglong2*)&sm_w[fl * 16 + 12];
                fma2(acc[0][0], xa, w01.x); fma2(acc[1][0], xb, w01.x);
                fma2(acc[0][1], xa, w01.y); fma2(acc[1][1], xb, w01.y);
                fma2(acc[0][2], xa, w23.x); fma2(acc[1][2], xb, w23.x);
                fma2(acc[0][3], xa, w23.y); fma2(acc[1][3], xb, w23.y);
                fma2(acc[0][4], xa, w45.x); fma2(acc[1][4], xb, w45.x);
                fma2(acc[0][5], xa, w45.y); fma2(acc[1][5], xb, w45.y);
                fma2(acc[0][6], xa, w67.x); fma2(acc[1][6], xb, w67.x);
                fma2(acc[0][7], xa, w67.y); fma2(acc[1][7], xb, w67.y);
            }
            __syncthreads();
        }

#pragma unroll
        for (int i = 0; i < 2; ++i) {
            int gq = q0 + qp * 2 + i;
            if (gq < NQ) {
#pragma unroll
                for (int h = 0; h < 8; ++h) {
                    float lo, hi; upk2(acc[i][h], lo, hi);
                    float2 o = {lo, hi};
                    *(float2*)&gB[(gq * 8 + h) * HW + k0 + kg * 2] = o;
                }
            }
        }
    }
}

// ---------------- softmax: probs = softmax(g_S + g_B + g_B2) -> g_S ----------------
__global__ void __launch_bounds__(256) softmax_kernel() {
    int q = blockIdx.x;
    int warp = threadIdx.x >> 5, lane = threadIdx.x & 31;
    float4* rp = (float4*)&g_S[(q * 8 + warp) * 1024];
    const float4* bp = (const float4*)&g_B[(q * 8 + warp) * 1024];
    const float4* bp2 = (const float4*)&g_B2[(q * 8 + warp) * 1024];

    float4 r[8];
#pragma unroll
    for (int j = 0; j < 8; ++j) {
        float4 a = rp[lane + 32 * j];
        float4 b = bp[lane + 32 * j];
        float4 c = bp2[lane + 32 * j];
        r[j].x = a.x + b.x + c.x; r[j].y = a.y + b.y + c.y;
        r[j].z = a.z + b.z + c.z; r[j].w = a.w + b.w + c.w;
    }

    float m = -1e30f;
#pragma unroll
    for (int j = 0; j < 8; ++j) {
        m = fmaxf(m, fmaxf(fmaxf(r[j].x, r[j].y), fmaxf(r[j].z, r[j].w)));
    }
#pragma unroll
    for (int o = 16; o; o >>= 1) m = fmaxf(m, __shfl_xor_sync(0xffffffffu, m, o));

    float s = 0.0f;
#pragma unroll
    for (int j = 0; j < 8; ++j) {
        r[j].x = __expf(r[j].x - m); s += r[j].x;
        r[j].y = __expf(r[j].y - m); s += r[j].y;
        r[j].z = __expf(r[j].z - m); s += r[j].z;
        r[j].w = __expf(r[j].w - m); s += r[j].w;
    }
#pragma unroll
    for (int o = 16; o; o >>= 1) s += __shfl_xor_sync(0xffffffffu, s, o);
    float inv = 1.0f / s;

#pragma unroll
    for (int j = 0; j < 8; ++j) {
        r[j].x *= inv; r[j].y *= inv; r[j].z *= inv; r[j].w *= inv;
        rp[lane + 32 * j] = r[j];
    }
}

// ---------------- PV GEMM (passing, unchanged) ----------------
__global__ void __launch_bounds__(128) pv_kernel() {
    __shared__ float Psm[16 * 64];
    __shared__ float vsm[64 * 64];

    int by = blockIdx.x;
    int q0 = blockIdx.y * 8;
    int t = threadIdx.x;
    int qg = t >> 5;
    int cp = t & 31;
    int h = cp >> 4;
    int cpl = cp & 15;

    ull acc2[2] = {0ull, 0ull};

    for (int kc = 0; kc < 1024; kc += 64) {
#pragma unroll
        for (int it = 0; it < 2; ++it) {
            int idx = t + it * 128;
            int row = idx >> 4, kk4 = idx & 15;
            int q_l = row & 7, hh = row >> 3;
            int gq = q0 + q_l; if (gq > NQ - 1) gq = NQ - 1;
            *(float4*)&Psm[(hh * 8 + q_l) * 64 + kk4 * 4] =
                *(const float4*)&g_S[(gq * 8 + 2 * by + hh) * 1024 + kc + kk4 * 4];
        }
#pragma unroll
        for (int it = 0; it < 8; ++it) {
            int idx = t + it * 128;
            int row = idx >> 4, c4 = idx & 15;
            *(float4*)&vsm[row * 64 + c4 * 4] =
                *(const float4*)&g_v[(kc + row) * 256 + by * 64 + c4 * 4];
        }
        __syncthreads();

#pragma unroll 4
        for (int kk = 0; kk < 64; kk += 4) {
            float4 p0 = *(const float4*)&Psm[(h * 8 + qg * 2 + 0) * 64 + kk];
            float4 p1 = *(const float4*)&Psm[(h * 8 + qg * 2 + 1) * 64 + kk];
            float p0a[4] = {p0.x, p0.y, p0.z, p0.w};
            float p1a[4] = {p1.x, p1.y, p1.z, p1.w};
#pragma unroll
            for (int j = 0; j < 4; ++j) {
                ull vv = *(const ull*)&vsm[(kk + j) * 64 + h * 32 + cpl * 2];
                fma2(acc2[0], pk2(p0a[j], p0a[j]), vv);
                fma2(acc2[1], pk2(p1a[j], p1a[j]), vv);
            }
        }
        __syncthreads();
    }

#pragma unroll
    for (int i = 0; i < 2; ++i) {
        int gq = q0 + qg * 2 + i;
        if (gq < NQ) {
            float lo, hi;
            upk2(acc2[i], lo, hi);
            float2 o = {lo, hi};
            *(float2*)&g_ctx[gq * 256 + by * 64 + h * 32 + cpl * 2] = o;
        }
    }
}

// ---------------- out-proj GEMM (passing, unchanged) ----------------
__global__ void __launch_bounds__(128) outproj_kernel(const float* __restrict__ bo,
                                                      float* __restrict__ out) {
    __shared__ float Csm[8 * 64];
    __shared__ float wsm[64 * 64];

    int by = blockIdx.x;
    int q0 = blockIdx.y * 8;
    int t = threadIdx.x;
    int qg = t >> 5;
    int cp = t & 31;

    ull acc2[2] = {0ull, 0ull};

    for (int kc = 0; kc < 256; kc += 64) {
        {
            int row = t >> 4, kk4 = t & 15;
            int gq = q0 + row; if (gq > NQ - 1) gq = NQ - 1;
            *(float4*)&Csm[row * 64 + kk4 * 4] =
                *(const float4*)&g_ctx[gq * 256 + kc + kk4 * 4];
        }
#pragma unroll
        for (int it = 0; it < 8; ++it) {
            int idx = t + it * 128;
            int row = idx >> 4, c4 = idx & 15;
            *(float4*)&wsm[row * 64 + c4 * 4] =
                *(const float4*)&g_wot[(kc + row) * 256 + by * 64 + c4 * 4];
        }
        __syncthreads();

#pragma unroll 4
        for (int kk = 0; kk < 64; kk += 4) {
            float4 c0 = *(const float4*)&Csm[(qg * 2 + 0) * 64 + kk];
            float4 c1 = *(const float4*)&Csm[(qg * 2 + 1) * 64 + kk];
            float c0a[4] = {c0.x, c0.y, c0.z, c0.w};
            float c1a[4] = {c1.x, c1.y, c1.z, c1.w};
#pragma unroll
            for (int j = 0; j < 4; ++j) {
                ull ww = *(const ull*)&wsm[(kk + j) * 64 + cp * 2];
                fma2(acc2[0], pk2(c0a[j], c0a[j]), ww);
                fma2(acc2[1], pk2(c1a[j], c1a[j]), ww);
            }
        }
        __syncthreads();
    }

    float b0 = bo[by * 64 + cp * 2], b1 = bo[by * 64 + cp * 2 + 1];
#pragma unroll
    for (int i = 0; i < 2; ++i) {
        int gq = q0 + qg * 2 + i;
        if (gq < NQ) {
            float lo, hi;
            upk2(acc2[i], lo, hi);
            float2 o = {lo + b0, hi + b1};
            *(float2*)&out[gq * 256 + cp * 2 + by * 64] = o;
        }
    }
}

// ---------------- launch ----------------
extern "C" void kernel_launch(void* const* d_in, const int* in_sizes, int n_in,
                              void* d_out, int out_size) {
    const float* raw_query = (const float*)d_in[0];
    const float* query_pos = (const float*)d_in[1];
    const float* ref_pts   = (const float*)d_in[2];
    const float* raw_src   = (const float*)d_in[3];
    const float* src_pos   = (const float*)d_in[4];
    const float* Wq = (const float*)d_in[5];
    const float* bq = (const float*)d_in[6];
    const float* Wk = (const float*)d_in[7];
    const float* bk = (const float*)d_in[8];
    const float* Wv = (const float*)d_in[9];
    const float* bv = (const float*)d_in[10];
    const float* Wo = (const float*)d_in[11];
    const float* bo = (const float*)d_in[12];
    const float* W1 = (const float*)d_in[13];
    const float* b1 = (const float*)d_in[14];
    const float* W2 = (const float*)d_in[15];
    float* out = (float*)d_out;

    prep_kernel<<<512, 128>>>(ref_pts, W1, b1, W2, Wo);            // 1

    qkv_gemm_kernel<<<dim3(37, 4), 256>>>(raw_query, query_pos, raw_src, src_pos,
                                          Wq, bq, Wk, bk, Wv, bv);  // 2

    score2_kernel<<<dim3(16, 38, 3), 128>>>();                      // 3 (ncu slot w/ -s5 lands later; fine)

    softmax_kernel<<<300, 256>>>();                                 // 4

    pv_kernel<<<dim3(4, 38), 128>>>();                              // 5

    outproj_kernel<<<dim3(4, 38), 128>>>(bo, out);                  // 6
}